// round 4
// baseline (speedup 1.0000x reference)
#include <cuda_runtime.h>
#include <math.h>

#define BB 2
#define NN 8192
#define CIN 64
#define CC 128
#define KK 16
#define EPSV 1e-5f

// ---------------- device scratch (no allocations allowed) -------------------
__device__ int   g_idx[BB*NN*KK];
__device__ float g_nf [(size_t)BB*NN*CC];
__device__ float g_aq [(size_t)BB*NN*CC];
__device__ float g_ak [(size_t)BB*NN*CC];
__device__ float g_v  [(size_t)BB*NN*CC];
__device__ float g_y5 [(size_t)BB*NN*CC];
__device__ float g_t1 [(size_t)BB*NN*KK*CC];     // 134 MB
__device__ float g_M  [CC*CC];
__device__ float g_Wq2[CC*CC];
__device__ float g_Wk2[CC*CC];
__device__ float g_ccv[CC];
__device__ float g_part1[1024*16];
__device__ float g_part2[8192*16];
__device__ float g_part3[512*16];
__device__ float g_sc1[BB*CC], g_sh1[BB*CC];
__device__ float g_sc2[BB*CC], g_sh2[BB*CC];
__device__ float g_sc3[BB*CC], g_sh3[BB*CC];

// 16-wide FMA step: one weight scalar times 16 positions in smem (pitch 20)
#define GSTEP16(wv, base) { \
  float4 x0=*(const float4*)((base));    float4 x1=*(const float4*)((base)+4); \
  float4 x2=*(const float4*)((base)+8);  float4 x3=*(const float4*)((base)+12); \
  acc[0]=fmaf(wv,x0.x,acc[0]);  acc[1]=fmaf(wv,x0.y,acc[1]); \
  acc[2]=fmaf(wv,x0.z,acc[2]);  acc[3]=fmaf(wv,x0.w,acc[3]); \
  acc[4]=fmaf(wv,x1.x,acc[4]);  acc[5]=fmaf(wv,x1.y,acc[5]); \
  acc[6]=fmaf(wv,x1.z,acc[6]);  acc[7]=fmaf(wv,x1.w,acc[7]); \
  acc[8]=fmaf(wv,x2.x,acc[8]);  acc[9]=fmaf(wv,x2.y,acc[9]); \
  acc[10]=fmaf(wv,x2.z,acc[10]);acc[11]=fmaf(wv,x2.w,acc[11]); \
  acc[12]=fmaf(wv,x3.x,acc[12]);acc[13]=fmaf(wv,x3.y,acc[13]); \
  acc[14]=fmaf(wv,x3.z,acc[14]);acc[15]=fmaf(wv,x3.w,acc[15]); }

extern __shared__ float dsm[];

// ---------------- kNN: warp per query, smem candidate tiles -----------------
__global__ void __launch_bounds__(256) k_knn(const float* __restrict__ xyz) {
  __shared__ float4 sp[1024];
  int b = blockIdx.y;
  int n = blockIdx.x * 8 + (threadIdx.x >> 5);
  int lane = threadIdx.x & 31;
  const float* xb = xyz + (size_t)b * 3 * NN;
  float qx = xb[n], qy = xb[NN + n], qz = xb[2 * NN + n];
  float qsq = __fadd_rn(__fadd_rn(__fmul_rn(qx,qx), __fmul_rn(qy,qy)), __fmul_rn(qz,qz));
  float bd[16]; int bi[16];
  #pragma unroll
  for (int i = 0; i < 16; i++) { bd[i] = 3.4e38f; bi[i] = 0; }
  float worstv = 3.4e38f; int worsts = 0;
  for (int t0 = 0; t0 < NN; t0 += 1024) {
    __syncthreads();
    for (int e = threadIdx.x; e < 1024; e += 256) {
      float x = xb[t0+e], y = xb[NN+t0+e], z = xb[2*NN+t0+e];
      float sq = __fadd_rn(__fadd_rn(__fmul_rn(x,x), __fmul_rn(y,y)), __fmul_rn(z,z));
      sp[e] = make_float4(x, y, z, sq);
    }
    __syncthreads();
    for (int j = lane; j < 1024; j += 32) {
      float4 c = sp[j];
      float inner = __fadd_rn(__fadd_rn(__fmul_rn(qx,c.x), __fmul_rn(qy,c.y)), __fmul_rn(qz,c.z));
      float d2 = __fsub_rn(__fadd_rn(qsq, c.w), __fmul_rn(2.0f, inner));
      if (d2 < worstv) {
        int ci = t0 + j;
        #pragma unroll
        for (int i = 0; i < 16; i++) if (i == worsts) { bd[i] = d2; bi[i] = ci; }
        worstv = bd[0]; worsts = 0;
        #pragma unroll
        for (int i = 1; i < 16; i++) if (bd[i] > worstv) { worstv = bd[i]; worsts = i; }
      }
    }
  }
  unsigned used = 0;
  int* outp = g_idx + ((size_t)b * NN + n) * KK;
  for (int r = 0; r < 16; r++) {
    float mv = 3.4e38f; int mi = -1, ms = 0;
    #pragma unroll
    for (int i = 0; i < 16; i++)
      if (!((used >> i) & 1) && bd[i] < mv) { mv = bd[i]; mi = bi[i]; ms = i; }
    float bv = mv; int bidx = mi; int bl = lane;
    #pragma unroll
    for (int off = 16; off >= 1; off >>= 1) {
      float ov = __shfl_xor_sync(0xffffffffu, bv, off);
      int   oi = __shfl_xor_sync(0xffffffffu, bidx, off);
      int   ol = __shfl_xor_sync(0xffffffffu, bl, off);
      if (ov < bv || (ov == bv && ol < bl)) { bv = ov; bidx = oi; bl = ol; }
    }
    if (lane == bl) used |= 1u << ms;
    if (lane == 0) outp[r] = bidx;
  }
}

// ---------------- pre conv: feat (B,64,N) -> nf (B,N,128) position-major ----
__global__ void __launch_bounds__(256) k_pre(const float* __restrict__ feat,
                                             const float* __restrict__ W,
                                             const float* __restrict__ bias) {
  __shared__ float wr[CC*65];
  __shared__ float buf[2*CIN*20];
  int tid = threadIdx.x, grp = tid >> 7, co = tid & 127;
  for (int e = tid; e < CC*CIN; e += 256) wr[(e>>6)*65 + (e&63)] = W[e];
  int b = blockIdx.y;
  int n0 = blockIdx.x*32 + grp*16;
  const float* fb = feat + (size_t)b * CIN * NN;
  for (int e = tid; e < 2*CIN*16; e += 256) {
    int g2 = e >> 10, ci = (e >> 4) & 63, p = e & 15;
    buf[g2*(CIN*20) + ci*20 + p] = fb[(size_t)ci*NN + blockIdx.x*32 + g2*16 + p];
  }
  __syncthreads();
  float* gb = buf + grp*(CIN*20);
  float acc[16]; float bv = bias[co];
  #pragma unroll
  for (int p = 0; p < 16; p++) acc[p] = bv;
  #pragma unroll 4
  for (int ci = 0; ci < CIN; ci++) { float w = wr[co*65+ci]; GSTEP16(w, gb + ci*20); }
  float* yb = g_nf + ((size_t)b*NN + n0) * CC;
  #pragma unroll
  for (int p = 0; p < 16; p++) yb[(size_t)p*CC + co] = acc[p];
}

// ---------------- weight folding ------------------------------------------
__global__ void k_combine(const float* __restrict__ A1, const float* __restrict__ Wq,
                          const float* __restrict__ Wk, const float* __restrict__ W2,
                          const float* __restrict__ a1b, const float* __restrict__ qb,
                          const float* __restrict__ kb, const float* __restrict__ p2b) {
  int z = blockIdx.x;
  if (z < 3) {
    const float* X = (z==0) ? Wq : ((z==1) ? Wk : W2);
    float* O = (z==0) ? g_Wq2 : ((z==1) ? g_Wk2 : g_M);
    for (int e = threadIdx.x; e < CC*CC; e += 256) {
      int o = e >> 7, c = e & 127;
      float s0=0.f, s1=0.f;
      for (int j = 0; j < CC; j += 2) {
        s0 = fmaf(A1[o*CC+j],   X[j*CC+c],     s0);
        s1 = fmaf(A1[o*CC+j+1], X[(j+1)*CC+c], s1);
      }
      O[e] = s0 + s1;
    }
  } else {
    for (int c = threadIdx.x; c < CC; c += 256) {
      float s = a1b[c];
      for (int j = 0; j < CC; j++) s = fmaf(A1[c*CC+j], qb[j]-kb[j]+p2b[j], s);
      g_ccv[c] = s;
    }
  }
}

// ---------------- GN1 stats over y1 = pos1_w@rel + pos1_b ------------------
__global__ void __launch_bounds__(256) k_gn1(const float* __restrict__ xyz,
                                             const float* __restrict__ p1w,
                                             const float* __restrict__ p1b) {
  __shared__ float sw[CC*4];
  __shared__ float sacc[16];
  int tid = threadIdx.x;
  for (int e = tid; e < CC*3; e += 256) sw[e] = p1w[e];
  for (int e = tid; e < CC; e += 256) sw[CC*3+e] = p1b[e];
  if (tid < 16) sacc[tid] = 0.f;
  __syncthreads();
  size_t r = (size_t)blockIdx.x*256 + tid;       // (b,n,k) row
  int b = (int)(r >> 17);
  int n = (int)((r >> 4) & 8191);
  int j = g_idx[r];
  const float* xb = xyz + (size_t)b*3*NN;
  float rx = xb[j]-xb[n], ry = xb[NN+j]-xb[NN+n], rz = xb[2*NN+j]-xb[2*NN+n];
  #pragma unroll
  for (int g = 0; g < 8; g++) {
    float s = 0.f, ss = 0.f;
    #pragma unroll
    for (int cc = 0; cc < 16; cc++) {
      int c = g*16 + cc;
      float y = fmaf(sw[c*3], rx, fmaf(sw[c*3+1], ry, fmaf(sw[c*3+2], rz, sw[CC*3+c])));
      s += y; ss = fmaf(y, y, ss);
    }
    atomicAdd(&sacc[g], s); atomicAdd(&sacc[8+g], ss);
  }
  __syncthreads();
  if (tid < 16) g_part1[blockIdx.x*16 + tid] = sacc[tid];
}

// ---------------- stats reduce -> per-(b,c) scale/shift --------------------
__global__ void k_reduce(int which, int nblkb, float invcnt,
                         const float* __restrict__ gamma, const float* __restrict__ beta) {
  const float* P = (which==0) ? g_part1 : ((which==1) ? g_part2 : g_part3);
  float* sc = (which==0) ? g_sc1 : ((which==1) ? g_sc2 : g_sc3);
  float* sh = (which==0) ? g_sh1 : ((which==1) ? g_sh2 : g_sh3);
  int b = blockIdx.x, tid = threadIdx.x;
  int s = tid & 15, grp = tid >> 4;
  double acc = 0.0;
  for (int blk = grp; blk < nblkb; blk += 16)
    acc += (double)P[((size_t)b*nblkb + blk)*16 + s];
  __shared__ double rr[16][17];
  __shared__ double fin[16];
  rr[grp][s] = acc;
  __syncthreads();
  if (tid < 16) { double t = 0.0; for (int i = 0; i < 16; i++) t += rr[i][tid]; fin[tid] = t; }
  __syncthreads();
  if (tid < CC) {
    int g8 = tid >> 4;
    double mean = fin[g8] * (double)invcnt;
    double var  = fin[8+g8] * (double)invcnt - mean*mean;
    float rstd = rsqrtf((float)var + EPSV);
    float scv = gamma[tid] * rstd;
    sc[b*CC+tid] = scv;
    sh[b*CC+tid] = beta[tid] - (float)mean * scv;
  }
}

// ---------------- generic position-major 128x128 conv ----------------------
__global__ void __launch_bounds__(256) k_conv_pm(const float* __restrict__ X,
                                                 const float* __restrict__ W,
                                                 const float* __restrict__ bias,
                                                 float* __restrict__ Y,
                                                 float* __restrict__ partials) {
  float* wr = dsm;                       // 128 x pitch129
  float* gb = dsm + CC*129;              // 2 x 128 x 20
  float* sacc = gb + 2*CC*20;            // 16
  int tid = threadIdx.x, grp = tid >> 7, co = tid & 127;
  for (int e = tid; e < CC*CC; e += 256) wr[(e>>7)*129 + (e&127)] = W[e];
  if (tid < 16) sacc[tid] = 0.f;
  size_t r0 = (size_t)blockIdx.x*32 + grp*16;
  float* g = gb + grp*(CC*20);
  #pragma unroll
  for (int p = 0; p < 16; p++) g[co*20+p] = X[(r0+p)*CC + co];
  __syncthreads();
  float acc[16]; float bv = bias[co];
  #pragma unroll
  for (int p = 0; p < 16; p++) acc[p] = bv;
  #pragma unroll 4
  for (int ci = 0; ci < CC; ci++) { float w = wr[co*129+ci]; GSTEP16(w, g + ci*20); }
  float s = 0.f, ss = 0.f;
  #pragma unroll
  for (int p = 0; p < 16; p++) { Y[(r0+p)*CC + co] = acc[p]; s += acc[p]; ss = fmaf(acc[p],acc[p],ss); }
  if (partials) {
    atomicAdd(&sacc[co>>4], s); atomicAdd(&sacc[8+(co>>4)], ss);
    __syncthreads();
    if (tid < 16) partials[blockIdx.x*16 + tid] = sacc[tid];
  }
}

// ---------------- fused att1: t1 = M@p1 + Aq - Ak_g + cvec, + GN2 stats ----
__global__ void __launch_bounds__(256) k_att1(const float* __restrict__ xyz,
                                              const float* __restrict__ p1w,
                                              const float* __restrict__ p1b) {
  float* wr = dsm;
  float* gb = dsm + CC*129;
  float* sacc = gb + 2*CC*20;            // 16
  float* rel = sacc + 16;                // 2 x 16 x 4
  int*   jsh = (int*)(rel + 2*64);       // 2 x 16
  int tid = threadIdx.x, grp = tid >> 7, co = tid & 127;
  for (int e = tid; e < CC*CC; e += 256) wr[(e>>7)*129 + (e&127)] = g_M[e];
  if (tid < 16) sacc[tid] = 0.f;
  int pg = blockIdx.x*2 + grp;
  int b = pg >> 13, n = pg & 8191;
  const float* xb = xyz + (size_t)b*3*NN;
  if (co < 16) {
    int j = g_idx[(size_t)pg*KK + co];
    jsh[grp*16+co] = j;
    float* rr = rel + grp*64 + co*4;
    rr[0] = xb[j]-xb[n]; rr[1] = xb[NN+j]-xb[NN+n]; rr[2] = xb[2*NN+j]-xb[2*NN+n];
  }
  __syncthreads();
  float w0 = p1w[co*3], w1 = p1w[co*3+1], w2 = p1w[co*3+2], pb = p1b[co];
  float s1 = g_sc1[b*CC+co], h1 = g_sh1[b*CC+co];
  float* g = gb + grp*(CC*20);
  #pragma unroll
  for (int k = 0; k < 16; k++) {
    float* rr = rel + grp*64 + k*4;
    float y = fmaf(w0, rr[0], fmaf(w1, rr[1], fmaf(w2, rr[2], pb)));
    y = s1*y + h1;
    g[co*20+k] = (y >= 0.f) ? y : 0.1f*y;
  }
  __syncthreads();
  float base = g_ccv[co] + g_aq[(size_t)pg*CC + co];
  float acc[16];
  #pragma unroll
  for (int k = 0; k < 16; k++) acc[k] = base;
  #pragma unroll 4
  for (int ci = 0; ci < CC; ci++) { float w = wr[co*129+ci]; GSTEP16(w, g + ci*20); }
  float s = 0.f, ss = 0.f;
  float* outp = g_t1 + (size_t)pg*KK*CC;
  #pragma unroll
  for (int k = 0; k < 16; k++) {
    int j = jsh[grp*16+k];
    float v = acc[k] - g_ak[((size_t)b*NN + j)*CC + co];
    outp[(size_t)k*CC + co] = v;
    s += v; ss = fmaf(v, v, ss);
  }
  atomicAdd(&sacc[co>>4], s); atomicAdd(&sacc[8+(co>>4)], ss);
  __syncthreads();
  if (tid < 16) g_part2[blockIdx.x*16 + tid] = sacc[tid];
}

// ---------------- fused att2 + softmax + V-agg + residual ------------------
__global__ void __launch_bounds__(256) k_att2(const float* __restrict__ W,
                                              const float* __restrict__ bias) {
  float* wr = dsm;
  float* gb = dsm + CC*129;
  float* sacc = gb + 2*CC*20;
  float* rel = sacc + 16;
  int*   jsh = (int*)(rel + 2*64);
  int tid = threadIdx.x, grp = tid >> 7, co = tid & 127;
  for (int e = tid; e < CC*CC; e += 256) wr[(e>>7)*129 + (e&127)] = W[e];
  int pg = blockIdx.x*2 + grp;
  int b = pg >> 13;
  if (co < 16) jsh[grp*16+co] = g_idx[(size_t)pg*KK + co];
  float s2 = g_sc2[b*CC+co], h2 = g_sh2[b*CC+co];
  const float* tp = g_t1 + (size_t)pg*KK*CC;
  float* g = gb + grp*(CC*20);
  #pragma unroll
  for (int k = 0; k < 16; k++) {
    float y = fmaf(s2, tp[(size_t)k*CC + co], h2);
    g[co*20+k] = (y >= 0.f) ? y : 0.1f*y;
  }
  __syncthreads();
  float acc[16]; float bv = bias[co];
  #pragma unroll
  for (int k = 0; k < 16; k++) acc[k] = bv;
  #pragma unroll 4
  for (int ci = 0; ci < CC; ci++) { float w = wr[co*129+ci]; GSTEP16(w, g + ci*20); }
  float m = acc[0];
  #pragma unroll
  for (int k = 1; k < 16; k++) m = fmaxf(m, acc[k]);
  float sum = 0.f;
  #pragma unroll
  for (int k = 0; k < 16; k++) { acc[k] = __expf(acc[k]-m); sum += acc[k]; }
  float inv = 1.f / sum;
  float o = 0.f;
  #pragma unroll
  for (int k = 0; k < 16; k++) {
    int j = jsh[grp*16+k];
    o = fmaf(acc[k]*inv, g_v[((size_t)b*NN + j)*CC + co], o);
  }
  g_y5[(size_t)pg*CC + co] = o + g_nf[(size_t)pg*CC + co];
}

// ---------------- final GN3 + lrelu + transpose to (B,C,N) -----------------
__global__ void k_final(float* __restrict__ out) {
  __shared__ float t[32][33];
  int b = blockIdx.z, c0 = blockIdx.y*32, n0 = blockIdx.x*32;
  int tx = threadIdx.x, ty = threadIdx.y;
  float scv = g_sc3[b*CC + c0 + tx], shv = g_sh3[b*CC + c0 + tx];
  #pragma unroll
  for (int i = 0; i < 4; i++) {
    int n = n0 + ty*4 + i;
    float x = g_aq[((size_t)b*NN + n)*CC + c0 + tx];
    float y = fmaf(scv, x, shv);
    t[tx][ty*4+i] = (y >= 0.f) ? y : 0.1f*y;
  }
  __syncthreads();
  #pragma unroll
  for (int i = 0; i < 4; i++) {
    int c = c0 + ty*4 + i;
    out[((size_t)b*CC + c)*NN + n0 + tx] = t[ty*4+i][tx];
  }
}

// ---------------- launch ----------------------------------------------------
extern "C" void kernel_launch(void* const* d_in, const int* in_sizes, int n_in,
                              void* d_out, int out_size) {
  const float* xyz    = (const float*)d_in[0];
  const float* feat   = (const float*)d_in[1];
  const float* pre_w  = (const float*)d_in[2];
  const float* pre_b  = (const float*)d_in[3];
  const float* wq_w   = (const float*)d_in[4];
  const float* wq_b   = (const float*)d_in[5];
  const float* wk_w   = (const float*)d_in[6];
  const float* wk_b   = (const float*)d_in[7];
  const float* wv_w   = (const float*)d_in[8];
  const float* wv_b   = (const float*)d_in[9];
  const float* pos1_w = (const float*)d_in[10];
  const float* pos1_b = (const float*)d_in[11];
  const float* pos1_g = (const float*)d_in[12];
  const float* pos1_be= (const float*)d_in[13];
  // pos2_w d_in[14], pos2_b d_in[15] consumed via folding
  const float* att1_w = (const float*)d_in[16];
  const float* att1_b = (const float*)d_in[17];
  const float* att1_g = (const float*)d_in[18];
  const float* att1_be= (const float*)d_in[19];
  const float* att2_w = (const float*)d_in[20];
  const float* att2_b = (const float*)d_in[21];
  const float* post_w = (const float*)d_in[22];
  const float* post_b = (const float*)d_in[23];
  const float* post_g = (const float*)d_in[24];
  const float* post_be= (const float*)d_in[25];
  float* out = (float*)d_out;

  const int SMEMB = (CC*129 + 2*CC*20 + 16 + 2*64 + 32 + 16) * 4;
  cudaFuncSetAttribute(k_conv_pm, cudaFuncAttributeMaxDynamicSharedMemorySize, SMEMB);
  cudaFuncSetAttribute(k_att1,    cudaFuncAttributeMaxDynamicSharedMemorySize, SMEMB);
  cudaFuncSetAttribute(k_att2,    cudaFuncAttributeMaxDynamicSharedMemorySize, SMEMB);

  void *p_nf, *p_aq, *p_ak, *p_v, *p_y5, *p_Wq2, *p_Wk2, *p_part3;
  cudaGetSymbolAddress(&p_nf,  g_nf);
  cudaGetSymbolAddress(&p_aq,  g_aq);
  cudaGetSymbolAddress(&p_ak,  g_ak);
  cudaGetSymbolAddress(&p_v,   g_v);
  cudaGetSymbolAddress(&p_y5,  g_y5);
  cudaGetSymbolAddress(&p_Wq2, g_Wq2);
  cudaGetSymbolAddress(&p_Wk2, g_Wk2);
  cudaGetSymbolAddress(&p_part3, g_part3);

  k_knn<<<dim3(NN/8, BB), 256>>>(xyz);
  k_pre<<<dim3(NN/32, BB), 256>>>(feat, pre_w, pre_b);
  k_combine<<<4, 256>>>(att1_w, wq_w, wk_w, (const float*)d_in[14],
                        att1_b, wq_b, wk_b, (const float*)d_in[15]);
  k_gn1<<<1024, 256>>>(xyz, pos1_w, pos1_b);
  k_reduce<<<2, 256>>>(0, 512, 1.f/2097152.f, pos1_g, pos1_be);
  k_conv_pm<<<512, 256, SMEMB>>>((const float*)p_nf, (const float*)p_Wq2, att1_b, (float*)p_aq, nullptr);
  k_conv_pm<<<512, 256, SMEMB>>>((const float*)p_nf, (const float*)p_Wk2, att1_b, (float*)p_ak, nullptr);
  k_conv_pm<<<512, 256, SMEMB>>>((const float*)p_nf, wv_w, wv_b, (float*)p_v, nullptr);
  k_att1<<<BB*NN/2, 256, SMEMB>>>(xyz, pos1_w, pos1_b);
  k_reduce<<<2, 256>>>(1, 4096, 1.f/2097152.f, att1_g, att1_be);
  k_att2<<<BB*NN/2, 256, SMEMB>>>(att2_w, att2_b);
  k_conv_pm<<<512, 256, SMEMB>>>((const float*)p_y5, post_w, post_b, (float*)p_aq, (float*)p_part3);
  k_reduce<<<2, 256>>>(2, 256, 1.f/131072.f, post_g, post_be);
  k_final<<<dim3(NN/32, CC/32, BB), dim3(32, 8)>>>(out);
}

// round 5
// speedup vs baseline: 1.1608x; 1.1608x over previous
#include <cuda_runtime.h>
#include <math.h>

#define BB 2
#define NN 8192
#define CIN 64
#define CC 128
#define KK 16
#define EPSV 1e-5f

__device__ int   g_idx[BB*NN*KK];
__device__ float g_nf [(size_t)BB*NN*CC];
__device__ float g_aq [(size_t)BB*NN*CC];
__device__ float g_ak [(size_t)BB*NN*CC];
__device__ float g_v  [(size_t)BB*NN*CC];
__device__ float g_y5 [(size_t)BB*NN*CC];
__device__ float g_t1 [(size_t)BB*NN*KK*CC];
__device__ float g_M  [CC*CC];
__device__ float g_Wq2[CC*CC];
__device__ float g_Wk2[CC*CC];
__device__ float g_ccv[CC];
__device__ float g_part1[1024*16];
__device__ float g_part2[BB*512*16];
__device__ float g_part3[BB*128*16];
__device__ float g_sc1[BB*CC], g_sh1[BB*CC];
__device__ float g_sc2[BB*CC], g_sh2[BB*CC];
__device__ float g_sc3[BB*CC], g_sh3[BB*CC];

#define GSTEP16(wv, base) { \
  float4 x0=*(const float4*)((base));    float4 x1=*(const float4*)((base)+4); \
  float4 x2=*(const float4*)((base)+8);  float4 x3=*(const float4*)((base)+12); \
  acc[0]=fmaf(wv,x0.x,acc[0]);  acc[1]=fmaf(wv,x0.y,acc[1]); \
  acc[2]=fmaf(wv,x0.z,acc[2]);  acc[3]=fmaf(wv,x0.w,acc[3]); \
  acc[4]=fmaf(wv,x1.x,acc[4]);  acc[5]=fmaf(wv,x1.y,acc[5]); \
  acc[6]=fmaf(wv,x1.z,acc[6]);  acc[7]=fmaf(wv,x1.w,acc[7]); \
  acc[8]=fmaf(wv,x2.x,acc[8]);  acc[9]=fmaf(wv,x2.y,acc[9]); \
  acc[10]=fmaf(wv,x2.z,acc[10]);acc[11]=fmaf(wv,x2.w,acc[11]); \
  acc[12]=fmaf(wv,x3.x,acc[12]);acc[13]=fmaf(wv,x3.y,acc[13]); \
  acc[14]=fmaf(wv,x3.z,acc[14]);acc[15]=fmaf(wv,x3.w,acc[15]); }

extern __shared__ float dsm[];

// ---------------- kNN -------------------------------------------------------
__global__ void __launch_bounds__(256) k_knn(const float* __restrict__ xyz) {
  __shared__ float4 sp[1024];
  int b = blockIdx.y;
  int n = blockIdx.x * 8 + (threadIdx.x >> 5);
  int lane = threadIdx.x & 31;
  const float* xb = xyz + (size_t)b * 3 * NN;
  float qx = xb[n], qy = xb[NN + n], qz = xb[2 * NN + n];
  float qsq = __fadd_rn(__fadd_rn(__fmul_rn(qx,qx), __fmul_rn(qy,qy)), __fmul_rn(qz,qz));
  float bd[16]; int bi[16];
  #pragma unroll
  for (int i = 0; i < 16; i++) { bd[i] = 3.4e38f; bi[i] = 0; }
  float worstv = 3.4e38f; int worsts = 0;
  for (int t0 = 0; t0 < NN; t0 += 1024) {
    __syncthreads();
    for (int e = threadIdx.x; e < 1024; e += 256) {
      float x = xb[t0+e], y = xb[NN+t0+e], z = xb[2*NN+t0+e];
      float sq = __fadd_rn(__fadd_rn(__fmul_rn(x,x), __fmul_rn(y,y)), __fmul_rn(z,z));
      sp[e] = make_float4(x, y, z, sq);
    }
    __syncthreads();
    for (int j = lane; j < 1024; j += 32) {
      float4 c = sp[j];
      float inner = __fadd_rn(__fadd_rn(__fmul_rn(qx,c.x), __fmul_rn(qy,c.y)), __fmul_rn(qz,c.z));
      float d2 = __fsub_rn(__fadd_rn(qsq, c.w), __fmul_rn(2.0f, inner));
      if (d2 < worstv) {
        int ci = t0 + j;
        #pragma unroll
        for (int i = 0; i < 16; i++) if (i == worsts) { bd[i] = d2; bi[i] = ci; }
        worstv = bd[0]; worsts = 0;
        #pragma unroll
        for (int i = 1; i < 16; i++) if (bd[i] > worstv) { worstv = bd[i]; worsts = i; }
      }
    }
  }
  unsigned used = 0;
  int* outp = g_idx + ((size_t)b * NN + n) * KK;
  for (int r = 0; r < 16; r++) {
    float mv = 3.4e38f; int mi = -1, ms = 0;
    #pragma unroll
    for (int i = 0; i < 16; i++)
      if (!((used >> i) & 1) && bd[i] < mv) { mv = bd[i]; mi = bi[i]; ms = i; }
    float bv = mv; int bidx = mi; int bl = lane;
    #pragma unroll
    for (int off = 16; off >= 1; off >>= 1) {
      float ov = __shfl_xor_sync(0xffffffffu, bv, off);
      int   oi = __shfl_xor_sync(0xffffffffu, bidx, off);
      int   ol = __shfl_xor_sync(0xffffffffu, bl, off);
      if (ov < bv || (ov == bv && ol < bl)) { bv = ov; bidx = oi; bl = ol; }
    }
    if (lane == bl) used |= 1u << ms;
    if (lane == 0) outp[r] = bidx;
  }
}

// ---------------- pre conv --------------------------------------------------
__global__ void __launch_bounds__(256) k_pre(const float* __restrict__ feat,
                                             const float* __restrict__ W,
                                             const float* __restrict__ bias) {
  __shared__ float wr[CC*65];
  __shared__ float buf[2*CIN*20];
  int tid = threadIdx.x, grp = tid >> 7, co = tid & 127;
  for (int e = tid; e < CC*CIN; e += 256) wr[(e>>6)*65 + (e&63)] = W[e];
  int b = blockIdx.y;
  int n0 = blockIdx.x*32 + grp*16;
  const float* fb = feat + (size_t)b * CIN * NN;
  for (int e = tid; e < 2*CIN*16; e += 256) {
    int g2 = e >> 10, ci = (e >> 4) & 63, p = e & 15;
    buf[g2*(CIN*20) + ci*20 + p] = fb[(size_t)ci*NN + blockIdx.x*32 + g2*16 + p];
  }
  __syncthreads();
  float* gb = buf + grp*(CIN*20);
  float acc[16]; float bv = bias[co];
  #pragma unroll
  for (int p = 0; p < 16; p++) acc[p] = bv;
  #pragma unroll 4
  for (int ci = 0; ci < CIN; ci++) { float w = wr[co*65+ci]; GSTEP16(w, gb + ci*20); }
  float* yb = g_nf + ((size_t)b*NN + n0) * CC;
  #pragma unroll
  for (int p = 0; p < 16; p++) yb[(size_t)p*CC + co] = acc[p];
}

// ---------------- weight folding --------------------------------------------
__global__ void k_combine(const float* __restrict__ A1, const float* __restrict__ Wq,
                          const float* __restrict__ Wk, const float* __restrict__ W2,
                          const float* __restrict__ a1b, const float* __restrict__ qb,
                          const float* __restrict__ kb, const float* __restrict__ p2b) {
  int z = blockIdx.x;
  if (z < 3) {
    const float* X = (z==0) ? Wq : ((z==1) ? Wk : W2);
    float* O = (z==0) ? g_Wq2 : ((z==1) ? g_Wk2 : g_M);
    for (int e = threadIdx.x; e < CC*CC; e += 256) {
      int o = e >> 7, c = e & 127;
      float s0=0.f, s1=0.f;
      for (int j = 0; j < CC; j += 2) {
        s0 = fmaf(A1[o*CC+j],   X[j*CC+c],     s0);
        s1 = fmaf(A1[o*CC+j+1], X[(j+1)*CC+c], s1);
      }
      O[e] = s0 + s1;
    }
  } else {
    for (int c = threadIdx.x; c < CC; c += 256) {
      float s = a1b[c];
      for (int j = 0; j < CC; j++) s = fmaf(A1[c*CC+j], qb[j]-kb[j]+p2b[j], s);
      g_ccv[c] = s;
    }
  }
}

// ---------------- GN1 stats (shuffle-reduced, no hot atomics) ---------------
__global__ void __launch_bounds__(256) k_gn1(const float* __restrict__ xyz,
                                             const float* __restrict__ p1w,
                                             const float* __restrict__ p1b) {
  __shared__ float sw[CC*4];
  __shared__ float sacc[16];
  int tid = threadIdx.x, lane = tid & 31;
  for (int e = tid; e < CC*3; e += 256) sw[e] = p1w[e];
  for (int e = tid; e < CC; e += 256) sw[CC*3+e] = p1b[e];
  if (tid < 16) sacc[tid] = 0.f;
  __syncthreads();
  size_t r = (size_t)blockIdx.x*256 + tid;
  int b = (int)(r >> 17);
  int n = (int)((r >> 4) & 8191);
  int j = g_idx[r];
  const float* xb = xyz + (size_t)b*3*NN;
  float rx = xb[j]-xb[n], ry = xb[NN+j]-xb[NN+n], rz = xb[2*NN+j]-xb[2*NN+n];
  #pragma unroll
  for (int g = 0; g < 8; g++) {
    float s = 0.f, ss = 0.f;
    #pragma unroll
    for (int cc = 0; cc < 16; cc++) {
      int c = g*16 + cc;
      float y = fmaf(sw[c*3], rx, fmaf(sw[c*3+1], ry, fmaf(sw[c*3+2], rz, sw[CC*3+c])));
      s += y; ss = fmaf(y, y, ss);
    }
    #pragma unroll
    for (int off = 16; off >= 1; off >>= 1) {
      s  += __shfl_down_sync(0xffffffffu, s, off);
      ss += __shfl_down_sync(0xffffffffu, ss, off);
    }
    if (lane == 0) { atomicAdd(&sacc[g], s); atomicAdd(&sacc[8+g], ss); }
  }
  __syncthreads();
  if (tid < 16) g_part1[blockIdx.x*16 + tid] = sacc[tid];
}

// ---------------- stats reduce ----------------------------------------------
__global__ void k_reduce(int which, int nblkb, float invcnt,
                         const float* __restrict__ gamma, const float* __restrict__ beta) {
  const float* P = (which==0) ? g_part1 : ((which==1) ? g_part2 : g_part3);
  float* sc = (which==0) ? g_sc1 : ((which==1) ? g_sc2 : g_sc3);
  float* sh = (which==0) ? g_sh1 : ((which==1) ? g_sh2 : g_sh3);
  int b = blockIdx.x, tid = threadIdx.x;
  int s = tid & 15, grp = tid >> 4;
  double acc = 0.0;
  for (int blk = grp; blk < nblkb; blk += 16)
    acc += (double)P[((size_t)b*nblkb + blk)*16 + s];
  __shared__ double rr[16][17];
  __shared__ double fin[16];
  rr[grp][s] = acc;
  __syncthreads();
  if (tid < 16) { double t = 0.0; for (int i = 0; i < 16; i++) t += rr[i][tid]; fin[tid] = t; }
  __syncthreads();
  if (tid < CC) {
    int g8 = tid >> 4;
    double mean = fin[g8] * (double)invcnt;
    double var  = fin[8+g8] * (double)invcnt - mean*mean;
    float rstd = rsqrtf((float)var + EPSV);
    float scv = gamma[tid] * rstd;
    sc[b*CC+tid] = scv;
    sh[b*CC+tid] = beta[tid] - (float)mean * scv;
  }
}

// ------- position-major 128x128 conv, 2 tiles per block (weights amortized) -
__global__ void __launch_bounds__(256) k_conv_pm(const float* __restrict__ X,
                                                 const float* __restrict__ W,
                                                 const float* __restrict__ bias,
                                                 float* __restrict__ Y,
                                                 float* __restrict__ partials) {
  float* wr = dsm;
  float* gb = dsm + CC*129;
  float* sacc = gb + 2*CC*20;
  int tid = threadIdx.x, grp = tid >> 7, co = tid & 127;
  int b = blockIdx.y;
  for (int e = tid; e < CC*CC; e += 256) wr[(e>>7)*129 + (e&127)] = W[e];
  if (tid < 16) sacc[tid] = 0.f;
  float bv = bias[co];
  float* g = gb + grp*(CC*20);
  float ts = 0.f, tss = 0.f;
  for (int it = 0; it < 2; it++) {
    size_t r0 = (size_t)b*NN + (size_t)(blockIdx.x*2 + it)*32 + grp*16;
    __syncthreads();
    #pragma unroll
    for (int p = 0; p < 16; p++) g[co*20+p] = X[(r0+p)*CC + co];
    __syncthreads();
    float acc[16];
    #pragma unroll
    for (int p = 0; p < 16; p++) acc[p] = bv;
    #pragma unroll 4
    for (int ci = 0; ci < CC; ci++) { float w = wr[co*129+ci]; GSTEP16(w, g + ci*20); }
    #pragma unroll
    for (int p = 0; p < 16; p++) { Y[(r0+p)*CC + co] = acc[p]; ts += acc[p]; tss = fmaf(acc[p],acc[p],tss); }
  }
  if (partials) {
    int lane = tid & 31;
    #pragma unroll
    for (int off = 16; off >= 1; off >>= 1) {
      ts  += __shfl_down_sync(0xffffffffu, ts, off);
      tss += __shfl_down_sync(0xffffffffu, tss, off);
    }
    // lane0 of each warp holds a 16-channel-group partial? No: threads in a warp span
    // one channel group only if co/16 constant — co = tid&127, warp = 32 consecutive co,
    // i.e. 2 channel groups per warp. Reduce over halves instead:
    // redo properly below
    __syncthreads();
  }
  if (partials) {
    // safe path: per-thread atomic into 16 slots is what we replaced; use half-warp shfl.
    // recompute: each half-warp (16 lanes) = one channel group.
    // NOTE: ts/tss were clobbered by the reduce above for lanes!=0; recompute cheaply:
    // Instead accumulate again from Y is wasteful — use __syncthreads-protected smem adds:
    ;
  }
  if (partials) {
    __syncthreads();
    if (tid < 16) partials[((size_t)b*gridDim.x + blockIdx.x)*16 + tid] = sacc[tid];
  }
}

// ---- att1: tile-looped; t1 = M@lrelu(gn1(pos1)) + Aq - Ak_g + cvec ---------
__global__ void __launch_bounds__(256) k_att1(const float* __restrict__ xyz,
                                              const float* __restrict__ p1w,
                                              const float* __restrict__ p1b) {
  float* wr = dsm;
  float* gb = dsm + CC*129;
  float* sacc = gb + 2*CC*20;
  float* rel = sacc + 16;
  int*   jsh = (int*)(rel + 2*64);
  int tid = threadIdx.x, grp = tid >> 7, co = tid & 127, lane = tid & 31;
  int b = blockIdx.y;
  for (int e = tid; e < CC*CC; e += 256) wr[(e>>7)*129 + (e&127)] = g_M[e];
  if (tid < 16) sacc[tid] = 0.f;
  float w0 = p1w[co*3], w1 = p1w[co*3+1], w2 = p1w[co*3+2], pb = p1b[co];
  float s1 = g_sc1[b*CC+co], h1 = g_sh1[b*CC+co];
  float cbase = g_ccv[co];
  const float* xb = xyz + (size_t)b*3*NN;
  float* g = gb + grp*(CC*20);
  float ts = 0.f, tss = 0.f;
  for (int it = 0; it < 8; it++) {
    int n = (blockIdx.x*8 + it)*2 + grp;
    __syncthreads();
    if (co < 16) {
      int j = g_idx[((size_t)b*NN + n)*KK + co];
      jsh[grp*16+co] = j;
      float* rr = rel + grp*64 + co*4;
      rr[0] = xb[j]-xb[n]; rr[1] = xb[NN+j]-xb[NN+n]; rr[2] = xb[2*NN+j]-xb[2*NN+n];
    }
    __syncthreads();
    #pragma unroll
    for (int k = 0; k < 16; k++) {
      float* rr = rel + grp*64 + k*4;
      float y = fmaf(w0, rr[0], fmaf(w1, rr[1], fmaf(w2, rr[2], pb)));
      y = s1*y + h1;
      g[co*20+k] = (y >= 0.f) ? y : 0.1f*y;
    }
    __syncthreads();
    float base = cbase + g_aq[((size_t)b*NN + n)*CC + co];
    float acc[16];
    #pragma unroll
    for (int k = 0; k < 16; k++) acc[k] = base;
    #pragma unroll 4
    for (int ci = 0; ci < CC; ci++) { float w = wr[co*129+ci]; GSTEP16(w, g + ci*20); }
    float* outp = g_t1 + ((size_t)b*NN + n)*KK*CC;
    #pragma unroll
    for (int k = 0; k < 16; k++) {
      int j = jsh[grp*16+k];
      float v = acc[k] - g_ak[((size_t)b*NN + j)*CC + co];
      outp[(size_t)k*CC + co] = v;
      ts += v; tss = fmaf(v, v, tss);
    }
  }
  // half-warp (=one channel group of 16) reduction, then one atomic per half-warp
  #pragma unroll
  for (int off = 8; off >= 1; off >>= 1) {
    ts  += __shfl_down_sync(0xffffffffu, ts, off, 16);
    tss += __shfl_down_sync(0xffffffffu, tss, off, 16);
  }
  if ((lane & 15) == 0) {
    int cg = co >> 4;
    atomicAdd(&sacc[cg], ts); atomicAdd(&sacc[8+cg], tss);
  }
  __syncthreads();
  if (tid < 16) g_part2[((size_t)b*gridDim.x + blockIdx.x)*16 + tid] = sacc[tid];
}

// ---- att2: tile-looped; + softmax + V-agg + residual -----------------------
__global__ void __launch_bounds__(256) k_att2(const float* __restrict__ W,
                                              const float* __restrict__ bias) {
  float* wr = dsm;
  float* gb = dsm + CC*129;
  float* sacc = gb + 2*CC*20;
  float* rel = sacc + 16;
  int*   jsh = (int*)(rel + 2*64);
  int tid = threadIdx.x, grp = tid >> 7, co = tid & 127;
  int b = blockIdx.y;
  for (int e = tid; e < CC*CC; e += 256) wr[(e>>7)*129 + (e&127)] = W[e];
  float s2 = g_sc2[b*CC+co], h2 = g_sh2[b*CC+co];
  float bv = bias[co];
  float* g = gb + grp*(CC*20);
  for (int it = 0; it < 8; it++) {
    int n = (blockIdx.x*8 + it)*2 + grp;
    __syncthreads();
    if (co < 16) jsh[grp*16+co] = g_idx[((size_t)b*NN + n)*KK + co];
    const float* tp = g_t1 + ((size_t)b*NN + n)*KK*CC;
    #pragma unroll
    for (int k = 0; k < 16; k++) {
      float y = fmaf(s2, tp[(size_t)k*CC + co], h2);
      g[co*20+k] = (y >= 0.f) ? y : 0.1f*y;
    }
    __syncthreads();
    float acc[16];
    #pragma unroll
    for (int k = 0; k < 16; k++) acc[k] = bv;
    #pragma unroll 4
    for (int ci = 0; ci < CC; ci++) { float w = wr[co*129+ci]; GSTEP16(w, g + ci*20); }
    float m = acc[0];
    #pragma unroll
    for (int k = 1; k < 16; k++) m = fmaxf(m, acc[k]);
    float sum = 0.f;
    #pragma unroll
    for (int k = 0; k < 16; k++) { acc[k] = __expf(acc[k]-m); sum += acc[k]; }
    float inv = 1.f / sum;
    float o = 0.f;
    #pragma unroll
    for (int k = 0; k < 16; k++) {
      int j = jsh[grp*16+k];
      o = fmaf(acc[k]*inv, g_v[((size_t)b*NN + j)*CC + co], o);
    }
    g_y5[((size_t)b*NN + n)*CC + co] = o + g_nf[((size_t)b*NN + n)*CC + co];
  }
}

// ---------------- final GN3 + lrelu + transpose -----------------------------
__global__ void k_final(float* __restrict__ out) {
  __shared__ float t[32][33];
  int b = blockIdx.z, c0 = blockIdx.y*32, n0 = blockIdx.x*32;
  int tx = threadIdx.x, ty = threadIdx.y;
  float scv = g_sc3[b*CC + c0 + tx], shv = g_sh3[b*CC + c0 + tx];
  #pragma unroll
  for (int i = 0; i < 4; i++) {
    int n = n0 + ty*4 + i;
    float x = g_aq[((size_t)b*NN + n)*CC + c0 + tx];
    float y = fmaf(scv, x, shv);
    t[tx][ty*4+i] = (y >= 0.f) ? y : 0.1f*y;
  }
  __syncthreads();
  #pragma unroll
  for (int i = 0; i < 4; i++) {
    int c = c0 + ty*4 + i;
    out[((size_t)b*CC + c)*NN + n0 + tx] = t[ty*4+i][tx];
  }
}

// post-conv stats fix: dedicated variant with half-warp shfl (avoids clobber bug)
__global__ void __launch_bounds__(256) k_conv_post(const float* __restrict__ X,
                                                   const float* __restrict__ W,
                                                   const float* __restrict__ bias,
                                                   float* __restrict__ Y) {
  float* wr = dsm;
  float* gb = dsm + CC*129;
  float* sacc = gb + 2*CC*20;
  int tid = threadIdx.x, grp = tid >> 7, co = tid & 127, lane = tid & 31;
  int b = blockIdx.y;
  for (int e = tid; e < CC*CC; e += 256) wr[(e>>7)*129 + (e&127)] = W[e];
  if (tid < 16) sacc[tid] = 0.f;
  float bv = bias[co];
  float* g = gb + grp*(CC*20);
  float ts = 0.f, tss = 0.f;
  for (int it = 0; it < 2; it++) {
    size_t r0 = (size_t)b*NN + (size_t)(blockIdx.x*2 + it)*32 + grp*16;
    __syncthreads();
    #pragma unroll
    for (int p = 0; p < 16; p++) g[co*20+p] = X[(r0+p)*CC + co];
    __syncthreads();
    float acc[16];
    #pragma unroll
    for (int p = 0; p < 16; p++) acc[p] = bv;
    #pragma unroll 4
    for (int ci = 0; ci < CC; ci++) { float w = wr[co*129+ci]; GSTEP16(w, g + ci*20); }
    #pragma unroll
    for (int p = 0; p < 16; p++) { Y[(r0+p)*CC + co] = acc[p]; ts += acc[p]; tss = fmaf(acc[p],acc[p],tss); }
  }
  #pragma unroll
  for (int off = 8; off >= 1; off >>= 1) {
    ts  += __shfl_down_sync(0xffffffffu, ts, off, 16);
    tss += __shfl_down_sync(0xffffffffu, tss, off, 16);
  }
  if ((lane & 15) == 0) {
    int cg = co >> 4;
    atomicAdd(&sacc[cg], ts); atomicAdd(&sacc[8+cg], tss);
  }
  __syncthreads();
  if (tid < 16) g_part3[((size_t)b*gridDim.x + blockIdx.x)*16 + tid] = sacc[tid];
}

// ---------------- launch ----------------------------------------------------
extern "C" void kernel_launch(void* const* d_in, const int* in_sizes, int n_in,
                              void* d_out, int out_size) {
  const float* xyz    = (const float*)d_in[0];
  const float* feat   = (const float*)d_in[1];
  const float* pre_w  = (const float*)d_in[2];
  const float* pre_b  = (const float*)d_in[3];
  const float* wq_w   = (const float*)d_in[4];
  const float* wq_b   = (const float*)d_in[5];
  const float* wk_w   = (const float*)d_in[6];
  const float* wk_b   = (const float*)d_in[7];
  const float* wv_w   = (const float*)d_in[8];
  const float* wv_b   = (const float*)d_in[9];
  const float* pos1_w = (const float*)d_in[10];
  const float* pos1_b = (const float*)d_in[11];
  const float* pos1_g = (const float*)d_in[12];
  const float* pos1_be= (const float*)d_in[13];
  const float* att1_b = (const float*)d_in[17];
  const float* att1_g = (const float*)d_in[18];
  const float* att1_be= (const float*)d_in[19];
  const float* att2_w = (const float*)d_in[20];
  const float* att2_b = (const float*)d_in[21];
  const float* post_w = (const float*)d_in[22];
  const float* post_b = (const float*)d_in[23];
  const float* post_g = (const float*)d_in[24];
  const float* post_be= (const float*)d_in[25];
  float* out = (float*)d_out;

  const int SMEMB = (CC*129 + 2*CC*20 + 16 + 2*64 + 32 + 16) * 4;
  cudaFuncSetAttribute(k_conv_pm,  cudaFuncAttributeMaxDynamicSharedMemorySize, SMEMB);
  cudaFuncSetAttribute(k_conv_post,cudaFuncAttributeMaxDynamicSharedMemorySize, SMEMB);
  cudaFuncSetAttribute(k_att1,     cudaFuncAttributeMaxDynamicSharedMemorySize, SMEMB);
  cudaFuncSetAttribute(k_att2,     cudaFuncAttributeMaxDynamicSharedMemorySize, SMEMB);

  void *p_nf, *p_aq, *p_ak, *p_v, *p_y5, *p_Wq2, *p_Wk2;
  cudaGetSymbolAddress(&p_nf,  g_nf);
  cudaGetSymbolAddress(&p_aq,  g_aq);
  cudaGetSymbolAddress(&p_ak,  g_ak);
  cudaGetSymbolAddress(&p_v,   g_v);
  cudaGetSymbolAddress(&p_y5,  g_y5);
  cudaGetSymbolAddress(&p_Wq2, g_Wq2);
  cudaGetSymbolAddress(&p_Wk2, g_Wk2);

  k_knn<<<dim3(NN/8, BB), 256>>>(xyz);
  k_pre<<<dim3(NN/32, BB), 256>>>(feat, pre_w, pre_b);
  k_combine<<<4, 256>>>((const float*)d_in[16], wq_w, wk_w, (const float*)d_in[14],
                        att1_b, wq_b, wk_b, (const float*)d_in[15]);
  k_gn1<<<1024, 256>>>(xyz, pos1_w, pos1_b);
  k_reduce<<<2, 256>>>(0, 512, 1.f/2097152.f, pos1_g, pos1_be);
  k_conv_pm<<<dim3(128, BB), 256, SMEMB>>>((const float*)p_nf, (const float*)p_Wq2, att1_b, (float*)p_aq, nullptr);
  k_conv_pm<<<dim3(128, BB), 256, SMEMB>>>((const float*)p_nf, (const float*)p_Wk2, att1_b, (float*)p_ak, nullptr);
  k_conv_pm<<<dim3(128, BB), 256, SMEMB>>>((const float*)p_nf, wv_w, wv_b, (float*)p_v, nullptr);
  k_att1<<<dim3(512, BB), 256, SMEMB>>>(xyz, pos1_w, pos1_b);
  k_reduce<<<2, 256>>>(1, 512, 1.f/2097152.f, att1_g, att1_be);
  k_att2<<<dim3(512, BB), 256, SMEMB>>>(att2_w, att2_b);
  k_conv_post<<<dim3(128, BB), 256, SMEMB>>>((const float*)p_y5, post_w, post_b, (float*)p_aq);
  k_reduce<<<2, 256>>>(2, 128, 1.f/131072.f, post_g, post_be);
  k_final<<<dim3(NN/32, CC/32, BB), dim3(32, 8)>>>(out);
}

// round 7
// speedup vs baseline: 1.2391x; 1.0675x over previous
#include <cuda_runtime.h>
#include <math.h>

#define BB 2
#define NN 8192
#define CIN 64
#define CC 128
#define KK 16
#define EPSV 1e-5f

__device__ int   g_idx[BB*NN*KK];
__device__ float g_nf [(size_t)BB*NN*CC];
__device__ float g_aq [(size_t)BB*NN*CC];
__device__ float g_ak [(size_t)BB*NN*CC];
__device__ float g_v  [(size_t)BB*NN*CC];
__device__ float g_y5 [(size_t)BB*NN*CC];
__device__ float g_t1 [(size_t)BB*NN*KK*CC];
__device__ float g_M  [CC*CC];
__device__ float g_Wq2[CC*CC];
__device__ float g_Wk2[CC*CC];
__device__ float g_ccv[CC];
__device__ float g_part1[1024*16];
__device__ float g_part2[BB*512*16];
__device__ float g_part3[BB*128*16];
__device__ float g_sc1[BB*CC], g_sh1[BB*CC];
__device__ float g_sc2[BB*CC], g_sh2[BB*CC];
__device__ float g_sc3[BB*CC], g_sh3[BB*CC];

#define WP 132            // weight smem pitch (floats)
#define XP 36             // x-tile smem pitch (floats)

#define GSTEP16(wv, base) { \
  float4 x0=*(const float4*)((base));    float4 x1=*(const float4*)((base)+4); \
  float4 x2=*(const float4*)((base)+8);  float4 x3=*(const float4*)((base)+12); \
  acc[0]=fmaf(wv,x0.x,acc[0]);  acc[1]=fmaf(wv,x0.y,acc[1]); \
  acc[2]=fmaf(wv,x0.z,acc[2]);  acc[3]=fmaf(wv,x0.w,acc[3]); \
  acc[4]=fmaf(wv,x1.x,acc[4]);  acc[5]=fmaf(wv,x1.y,acc[5]); \
  acc[6]=fmaf(wv,x1.z,acc[6]);  acc[7]=fmaf(wv,x1.w,acc[7]); \
  acc[8]=fmaf(wv,x2.x,acc[8]);  acc[9]=fmaf(wv,x2.y,acc[9]); \
  acc[10]=fmaf(wv,x2.z,acc[10]);acc[11]=fmaf(wv,x2.w,acc[11]); \
  acc[12]=fmaf(wv,x3.x,acc[12]);acc[13]=fmaf(wv,x3.y,acc[13]); \
  acc[14]=fmaf(wv,x3.z,acc[14]);acc[15]=fmaf(wv,x3.w,acc[15]); }

// 4x4 outer-product step
#define OSTEP(w4, x4) { \
  a0.x=fmaf(w4.x,x4.x,a0.x); a0.y=fmaf(w4.y,x4.x,a0.y); a0.z=fmaf(w4.z,x4.x,a0.z); a0.w=fmaf(w4.w,x4.x,a0.w); \
  a1.x=fmaf(w4.x,x4.y,a1.x); a1.y=fmaf(w4.y,x4.y,a1.y); a1.z=fmaf(w4.z,x4.y,a1.z); a1.w=fmaf(w4.w,x4.y,a1.w); \
  a2.x=fmaf(w4.x,x4.z,a2.x); a2.y=fmaf(w4.y,x4.z,a2.y); a2.z=fmaf(w4.z,x4.z,a2.z); a2.w=fmaf(w4.w,x4.z,a2.w); \
  a3.x=fmaf(w4.x,x4.w,a3.x); a3.y=fmaf(w4.y,x4.w,a3.y); a3.z=fmaf(w4.z,x4.w,a3.z); a3.w=fmaf(w4.w,x4.w,a3.w); }

extern __shared__ float dsm[];

// ---------------- kNN -------------------------------------------------------
__global__ void __launch_bounds__(256) k_knn(const float* __restrict__ xyz) {
  __shared__ float4 sp[1024];
  int b = blockIdx.y;
  int n = blockIdx.x * 8 + (threadIdx.x >> 5);
  int lane = threadIdx.x & 31;
  const float* xb = xyz + (size_t)b * 3 * NN;
  float qx = xb[n], qy = xb[NN + n], qz = xb[2 * NN + n];
  float qsq = __fadd_rn(__fadd_rn(__fmul_rn(qx,qx), __fmul_rn(qy,qy)), __fmul_rn(qz,qz));
  float bd[16]; int bi[16];
  #pragma unroll
  for (int i = 0; i < 16; i++) { bd[i] = 3.4e38f; bi[i] = 0; }
  float worstv = 3.4e38f; int worsts = 0;
  for (int t0 = 0; t0 < NN; t0 += 1024) {
    __syncthreads();
    for (int e = threadIdx.x; e < 1024; e += 256) {
      float x = xb[t0+e], y = xb[NN+t0+e], z = xb[2*NN+t0+e];
      float sq = __fadd_rn(__fadd_rn(__fmul_rn(x,x), __fmul_rn(y,y)), __fmul_rn(z,z));
      sp[e] = make_float4(x, y, z, sq);
    }
    __syncthreads();
    for (int j = lane; j < 1024; j += 32) {
      float4 c = sp[j];
      float inner = __fadd_rn(__fadd_rn(__fmul_rn(qx,c.x), __fmul_rn(qy,c.y)), __fmul_rn(qz,c.z));
      float d2 = __fsub_rn(__fadd_rn(qsq, c.w), __fmul_rn(2.0f, inner));
      if (d2 < worstv) {
        int ci = t0 + j;
        #pragma unroll
        for (int i = 0; i < 16; i++) if (i == worsts) { bd[i] = d2; bi[i] = ci; }
        worstv = bd[0]; worsts = 0;
        #pragma unroll
        for (int i = 1; i < 16; i++) if (bd[i] > worstv) { worstv = bd[i]; worsts = i; }
      }
    }
  }
  unsigned used = 0;
  int* outp = g_idx + ((size_t)b * NN + n) * KK;
  for (int r = 0; r < 16; r++) {
    float mv = 3.4e38f; int mi = -1, ms = 0;
    #pragma unroll
    for (int i = 0; i < 16; i++)
      if (!((used >> i) & 1) && bd[i] < mv) { mv = bd[i]; mi = bi[i]; ms = i; }
    float bv = mv; int bidx = mi; int bl = lane;
    #pragma unroll
    for (int off = 16; off >= 1; off >>= 1) {
      float ov = __shfl_xor_sync(0xffffffffu, bv, off);
      int   oi = __shfl_xor_sync(0xffffffffu, bidx, off);
      int   ol = __shfl_xor_sync(0xffffffffu, bl, off);
      if (ov < bv || (ov == bv && ol < bl)) { bv = ov; bidx = oi; bl = ol; }
    }
    if (lane == bl) used |= 1u << ms;
    if (lane == 0) outp[r] = bidx;
  }
}

// ---------------- pre conv --------------------------------------------------
__global__ void __launch_bounds__(256) k_pre(const float* __restrict__ feat,
                                             const float* __restrict__ W,
                                             const float* __restrict__ bias) {
  __shared__ float wr[CC*65];
  __shared__ float buf[2*CIN*20];
  int tid = threadIdx.x, grp = tid >> 7, co = tid & 127;
  for (int e = tid; e < CC*CIN; e += 256) wr[(e>>6)*65 + (e&63)] = W[e];
  int b = blockIdx.y;
  int n0 = blockIdx.x*32 + grp*16;
  const float* fb = feat + (size_t)b * CIN * NN;
  for (int e = tid; e < 2*CIN*16; e += 256) {
    int g2 = e >> 10, ci = (e >> 4) & 63, p = e & 15;
    buf[g2*(CIN*20) + ci*20 + p] = fb[(size_t)ci*NN + blockIdx.x*32 + g2*16 + p];
  }
  __syncthreads();
  float* gb = buf + grp*(CIN*20);
  float acc[16]; float bv = bias[co];
  #pragma unroll
  for (int p = 0; p < 16; p++) acc[p] = bv;
  #pragma unroll 4
  for (int ci = 0; ci < CIN; ci++) { float w = wr[co*65+ci]; GSTEP16(w, gb + ci*20); }
  float* yb = g_nf + ((size_t)b*NN + n0) * CC;
  #pragma unroll
  for (int p = 0; p < 16; p++) yb[(size_t)p*CC + co] = acc[p];
}

// ---------------- weight folding --------------------------------------------
__global__ void k_combine(const float* __restrict__ A1, const float* __restrict__ Wq,
                          const float* __restrict__ Wk, const float* __restrict__ W2,
                          const float* __restrict__ a1b, const float* __restrict__ qb,
                          const float* __restrict__ kb, const float* __restrict__ p2b) {
  int z = blockIdx.x;
  if (z < 3) {
    const float* X = (z==0) ? Wq : ((z==1) ? Wk : W2);
    float* O = (z==0) ? g_Wq2 : ((z==1) ? g_Wk2 : g_M);
    for (int e = threadIdx.x; e < CC*CC; e += 256) {
      int o = e >> 7, c = e & 127;
      float s0=0.f, s1=0.f;
      for (int j = 0; j < CC; j += 2) {
        s0 = fmaf(A1[o*CC+j],   X[j*CC+c],     s0);
        s1 = fmaf(A1[o*CC+j+1], X[(j+1)*CC+c], s1);
      }
      O[e] = s0 + s1;
    }
  } else {
    for (int c = threadIdx.x; c < CC; c += 256) {
      float s = a1b[c];
      for (int j = 0; j < CC; j++) s = fmaf(A1[c*CC+j], qb[j]-kb[j]+p2b[j], s);
      g_ccv[c] = s;
    }
  }
}

// ---------------- GN1 stats --------------------------------------------------
__global__ void __launch_bounds__(256) k_gn1(const float* __restrict__ xyz,
                                             const float* __restrict__ p1w,
                                             const float* __restrict__ p1b) {
  __shared__ float sw[CC*4];
  __shared__ float sacc[16];
  int tid = threadIdx.x, lane = tid & 31;
  for (int e = tid; e < CC*3; e += 256) sw[e] = p1w[e];
  for (int e = tid; e < CC; e += 256) sw[CC*3+e] = p1b[e];
  if (tid < 16) sacc[tid] = 0.f;
  __syncthreads();
  size_t r = (size_t)blockIdx.x*256 + tid;
  int b = (int)(r >> 17);
  int n = (int)((r >> 4) & 8191);
  int j = g_idx[r];
  const float* xb = xyz + (size_t)b*3*NN;
  float rx = xb[j]-xb[n], ry = xb[NN+j]-xb[NN+n], rz = xb[2*NN+j]-xb[2*NN+n];
  #pragma unroll
  for (int g = 0; g < 8; g++) {
    float s = 0.f, ss = 0.f;
    #pragma unroll
    for (int cc = 0; cc < 16; cc++) {
      int c = g*16 + cc;
      float y = fmaf(sw[c*3], rx, fmaf(sw[c*3+1], ry, fmaf(sw[c*3+2], rz, sw[CC*3+c])));
      s += y; ss = fmaf(y, y, ss);
    }
    #pragma unroll
    for (int off = 16; off >= 1; off >>= 1) {
      s  += __shfl_down_sync(0xffffffffu, s, off);
      ss += __shfl_down_sync(0xffffffffu, ss, off);
    }
    if (lane == 0) { atomicAdd(&sacc[g], s); atomicAdd(&sacc[8+g], ss); }
  }
  __syncthreads();
  if (tid < 16) g_part1[blockIdx.x*16 + tid] = sacc[tid];
}

// ---------------- stats reduce ----------------------------------------------
__global__ void k_reduce(int which, int nblkb, float invcnt,
                         const float* __restrict__ gamma, const float* __restrict__ beta) {
  const float* P = (which==0) ? g_part1 : ((which==1) ? g_part2 : g_part3);
  float* sc = (which==0) ? g_sc1 : ((which==1) ? g_sc2 : g_sc3);
  float* sh = (which==0) ? g_sh1 : ((which==1) ? g_sh2 : g_sh3);
  int b = blockIdx.x, tid = threadIdx.x;
  int s = tid & 15, grp = tid >> 4;
  double acc = 0.0;
  for (int blk = grp; blk < nblkb; blk += 16)
    acc += (double)P[((size_t)b*nblkb + blk)*16 + s];
  __shared__ double rr[16][17];
  __shared__ double fin[16];
  rr[grp][s] = acc;
  __syncthreads();
  if (tid < 16) { double t = 0.0; for (int i = 0; i < 16; i++) t += rr[i][tid]; fin[tid] = t; }
  __syncthreads();
  if (tid < CC) {
    int g8 = tid >> 4;
    double mean = fin[g8] * (double)invcnt;
    double var  = fin[8+g8] * (double)invcnt - mean*mean;
    float rstd = rsqrtf((float)var + EPSV);
    float scv = gamma[tid] * rstd;
    sc[b*CC+tid] = scv;
    sh[b*CC+tid] = beta[tid] - (float)mean * scv;
  }
}

// ---------------- conv (unchanged, 2 tiles/block) ----------------------------
__global__ void __launch_bounds__(256) k_conv_pm(const float* __restrict__ X,
                                                 const float* __restrict__ W,
                                                 const float* __restrict__ bias,
                                                 float* __restrict__ Y) {
  float* wr = dsm;
  float* gb = dsm + CC*129;
  int tid = threadIdx.x, grp = tid >> 7, co = tid & 127;
  int b = blockIdx.y;
  for (int e = tid; e < CC*CC; e += 256) wr[(e>>7)*129 + (e&127)] = W[e];
  float bv = bias[co];
  float* g = gb + grp*(CC*20);
  for (int it = 0; it < 2; it++) {
    size_t r0 = (size_t)b*NN + (size_t)(blockIdx.x*2 + it)*32 + grp*16;
    __syncthreads();
    #pragma unroll
    for (int p = 0; p < 16; p++) g[co*20+p] = X[(r0+p)*CC + co];
    __syncthreads();
    float acc[16];
    #pragma unroll
    for (int p = 0; p < 16; p++) acc[p] = bv;
    #pragma unroll 4
    for (int ci = 0; ci < CC; ci++) { float w = wr[co*129+ci]; GSTEP16(w, g + ci*20); }
    #pragma unroll
    for (int p = 0; p < 16; p++) Y[(r0+p)*CC + co] = acc[p];
  }
}

// ---- att1: balanced 4co x 4pos blocking; t1 = M@x + Aq - Ak_g + cvec -------
__global__ void __launch_bounds__(256) k_att1(const float* __restrict__ xyz,
                                              const float* __restrict__ p1w,
                                              const float* __restrict__ p1b) {
  float* wT  = dsm;                 // [ci][co] pitch WP
  float* gx  = dsm + CC*WP;         // [ci][pos] pitch XP
  float* rels= gx + CC*XP;          // 32*4
  int*   jsh = (int*)(rels + 128);  // 32
  int tid = threadIdx.x, lane = tid & 31, w = tid >> 5;
  int pg = tid & 7, cg = tid >> 3;  // pos=4*pg, co=4*cg
  int b = blockIdx.y;
  for (int e = tid; e < CC*CC; e += 256) wT[(e&127)*WP + (e>>7)] = g_M[e];
  int cb = tid & 127, half = tid >> 7;  // build-phase mapping
  float w0 = p1w[cb*3], w1 = p1w[cb*3+1], w2 = p1w[cb*3+2], pb = p1b[cb];
  float s1 = g_sc1[b*CC+cb], h1 = g_sh1[b*CC+cb];
  float4 cv = *(const float4*)(g_ccv + cg*4);
  const float* xb = xyz + (size_t)b*3*NN;
  float ts = 0.f, tss = 0.f;
  for (int it = 0; it < 8; it++) {
    int n0 = (blockIdx.x*8 + it)*2;
    size_t r0 = ((size_t)b*NN + n0)*16;
    __syncthreads();
    if (tid < 32) {
      int j = g_idx[r0 + tid];
      jsh[tid] = j;
      int nq = n0 + (tid >> 4);
      rels[tid*4+0] = xb[j]-xb[nq];
      rels[tid*4+1] = xb[NN+j]-xb[NN+nq];
      rels[tid*4+2] = xb[2*NN+j]-xb[2*NN+nq];
    }
    __syncthreads();
    #pragma unroll
    for (int i = 0; i < 16; i++) {
      int pos = half*16 + i;
      float y = fmaf(w0, rels[pos*4], fmaf(w1, rels[pos*4+1], fmaf(w2, rels[pos*4+2], pb)));
      y = s1*y + h1;
      gx[cb*XP + pos] = (y >= 0.f) ? y : 0.1f*y;
    }
    __syncthreads();
    float4 a0 = make_float4(0,0,0,0), a1 = a0, a2 = a0, a3 = a0;
    #pragma unroll 8
    for (int ci = 0; ci < CC; ci++) {
      float4 w4 = *(const float4*)(wT + ci*WP + cg*4);
      float4 x4 = *(const float4*)(gx + ci*XP + pg*4);
      OSTEP(w4, x4);
    }
    float4 av[4] = {a0, a1, a2, a3};
    #pragma unroll
    for (int p = 0; p < 4; p++) {
      int pos = pg*4 + p;
      int nq = n0 + (pos >> 4);
      int j = jsh[pos];
      float4 aq = *(const float4*)(g_aq + ((size_t)b*NN + nq)*CC + cg*4);
      float4 ak = *(const float4*)(g_ak + ((size_t)b*NN + j)*CC + cg*4);
      float4 v;
      v.x = av[p].x + cv.x + aq.x - ak.x;
      v.y = av[p].y + cv.y + aq.y - ak.y;
      v.z = av[p].z + cv.z + aq.z - ak.z;
      v.w = av[p].w + cv.w + aq.w - ak.w;
      *(float4*)(g_t1 + (r0 + pos)*CC + cg*4) = v;
      ts += v.x + v.y + v.z + v.w;
      tss = fmaf(v.x,v.x,fmaf(v.y,v.y,fmaf(v.z,v.z,fmaf(v.w,v.w,tss))));
    }
  }
  // warp w covers exactly channel group w (co in [16w,16w+16))
  #pragma unroll
  for (int off = 16; off >= 1; off >>= 1) {
    ts  += __shfl_down_sync(0xffffffffu, ts, off);
    tss += __shfl_down_sync(0xffffffffu, tss, off);
  }
  if (lane == 0) {
    g_part2[((size_t)b*gridDim.x + blockIdx.x)*16 + w]     = ts;
    g_part2[((size_t)b*gridDim.x + blockIdx.x)*16 + 8 + w] = tss;
  }
}

// ---- att2: balanced blocking + width-4 shuffle softmax + V-agg + residual --
__global__ void __launch_bounds__(256) k_att2(const float* __restrict__ W,
                                              const float* __restrict__ bias) {
  float* wT  = dsm;
  float* gx  = dsm + CC*WP;
  int*   jsh = (int*)(gx + CC*XP);
  int tid = threadIdx.x;
  int pg = tid & 7, cg = tid >> 3;
  int b = blockIdx.y;
  for (int e = tid; e < CC*CC; e += 256) wT[(e&127)*WP + (e>>7)] = W[e];
  int cb = tid & 127, half = tid >> 7;
  float s2 = g_sc2[b*CC+cb], h2 = g_sh2[b*CC+cb];
  float4 b4 = *(const float4*)(bias + cg*4);
  for (int it = 0; it < 8; it++) {
    int n0 = (blockIdx.x*8 + it)*2;
    size_t r0 = ((size_t)b*NN + n0)*16;
    __syncthreads();
    if (tid < 32) jsh[tid] = g_idx[r0 + tid];
    {
      const float* tp = g_t1 + r0*CC + cb;
      #pragma unroll
      for (int i = 0; i < 16; i++) {
        int pos = half*16 + i;
        float y = fmaf(s2, tp[(size_t)pos*CC], h2);
        gx[cb*XP + pos] = (y >= 0.f) ? y : 0.1f*y;
      }
    }
    __syncthreads();
    float4 a0 = b4, a1 = b4, a2 = b4, a3 = b4;
    #pragma unroll 8
    for (int ci = 0; ci < CC; ci++) {
      float4 w4 = *(const float4*)(wT + ci*WP + cg*4);
      float4 x4 = *(const float4*)(gx + ci*XP + pg*4);
      OSTEP(w4, x4);
    }
    float4 av[4] = {a0, a1, a2, a3};
    // max over the 16 k of this n (4 in-thread + 4 lanes of width-4 group)
    float4 m4;
    m4.x = fmaxf(fmaxf(av[0].x, av[1].x), fmaxf(av[2].x, av[3].x));
    m4.y = fmaxf(fmaxf(av[0].y, av[1].y), fmaxf(av[2].y, av[3].y));
    m4.z = fmaxf(fmaxf(av[0].z, av[1].z), fmaxf(av[2].z, av[3].z));
    m4.w = fmaxf(fmaxf(av[0].w, av[1].w), fmaxf(av[2].w, av[3].w));
    #pragma unroll
    for (int off = 1; off <= 2; off <<= 1) {
      m4.x = fmaxf(m4.x, __shfl_xor_sync(0xffffffffu, m4.x, off, 4));
      m4.y = fmaxf(m4.y, __shfl_xor_sync(0xffffffffu, m4.y, off, 4));
      m4.z = fmaxf(m4.z, __shfl_xor_sync(0xffffffffu, m4.z, off, 4));
      m4.w = fmaxf(m4.w, __shfl_xor_sync(0xffffffffu, m4.w, off, 4));
    }
    float4 sm = make_float4(0,0,0,0);
    #pragma unroll
    for (int p = 0; p < 4; p++) {
      av[p].x = __expf(av[p].x - m4.x); sm.x += av[p].x;
      av[p].y = __expf(av[p].y - m4.y); sm.y += av[p].y;
      av[p].z = __expf(av[p].z - m4.z); sm.z += av[p].z;
      av[p].w = __expf(av[p].w - m4.w); sm.w += av[p].w;
    }
    #pragma unroll
    for (int off = 1; off <= 2; off <<= 1) {
      sm.x += __shfl_xor_sync(0xffffffffu, sm.x, off, 4);
      sm.y += __shfl_xor_sync(0xffffffffu, sm.y, off, 4);
      sm.z += __shfl_xor_sync(0xffffffffu, sm.z, off, 4);
      sm.w += __shfl_xor_sync(0xffffffffu, sm.w, off, 4);
    }
    float4 o = make_float4(0,0,0,0);
    #pragma unroll
    for (int p = 0; p < 4; p++) {
      int j = jsh[pg*4 + p];
      float4 vv = *(const float4*)(g_v + ((size_t)b*NN + j)*CC + cg*4);
      o.x = fmaf(av[p].x, vv.x, o.x);
      o.y = fmaf(av[p].y, vv.y, o.y);
      o.z = fmaf(av[p].z, vv.z, o.z);
      o.w = fmaf(av[p].w, vv.w, o.w);
    }
    #pragma unroll
    for (int off = 1; off <= 2; off <<= 1) {
      o.x += __shfl_xor_sync(0xffffffffu, o.x, off, 4);
      o.y += __shfl_xor_sync(0xffffffffu, o.y, off, 4);
      o.z += __shfl_xor_sync(0xffffffffu, o.z, off, 4);
      o.w += __shfl_xor_sync(0xffffffffu, o.w, off, 4);
    }
    if ((pg & 3) == 0) {
      int nq = n0 + (pg >> 2);
      float4 nf = *(const float4*)(g_nf + ((size_t)b*NN + nq)*CC + cg*4);
      float4 r;
      r.x = o.x/sm.x + nf.x; r.y = o.y/sm.y + nf.y;
      r.z = o.z/sm.z + nf.z; r.w = o.w/sm.w + nf.w;
      *(float4*)(g_y5 + ((size_t)b*NN + nq)*CC + cg*4) = r;
    }
  }
}

// ---------------- post conv + stats ------------------------------------------
__global__ void __launch_bounds__(256) k_conv_post(const float* __restrict__ X,
                                                   const float* __restrict__ W,
                                                   const float* __restrict__ bias,
                                                   float* __restrict__ Y) {
  float* wr = dsm;
  float* gb = dsm + CC*129;
  float* sacc = gb + 2*CC*20;
  int tid = threadIdx.x, grp = tid >> 7, co = tid & 127, lane = tid & 31;
  int b = blockIdx.y;
  for (int e = tid; e < CC*CC; e += 256) wr[(e>>7)*129 + (e&127)] = W[e];
  if (tid < 16) sacc[tid] = 0.f;
  float bv = bias[co];
  float* g = gb + grp*(CC*20);
  float ts = 0.f, tss = 0.f;
  for (int it = 0; it < 2; it++) {
    size_t r0 = (size_t)b*NN + (size_t)(blockIdx.x*2 + it)*32 + grp*16;
    __syncthreads();
    #pragma unroll
    for (int p = 0; p < 16; p++) g[co*20+p] = X[(r0+p)*CC + co];
    __syncthreads();
    float acc[16];
    #pragma unroll
    for (int p = 0; p < 16; p++) acc[p] = bv;
    #pragma unroll 4
    for (int ci = 0; ci < CC; ci++) { float w = wr[co*129+ci]; GSTEP16(w, g + ci*20); }
    #pragma unroll
    for (int p = 0; p < 16; p++) { Y[(r0+p)*CC + co] = acc[p]; ts += acc[p]; tss = fmaf(acc[p],acc[p],tss); }
  }
  #pragma unroll
  for (int off = 8; off >= 1; off >>= 1) {
    ts  += __shfl_down_sync(0xffffffffu, ts, off, 16);
    tss += __shfl_down_sync(0xffffffffu, tss, off, 16);
  }
  if ((lane & 15) == 0) {
    int cgg = co >> 4;
    atomicAdd(&sacc[cgg], ts); atomicAdd(&sacc[8+cgg], tss);
  }
  __syncthreads();
  if (tid < 16) g_part3[((size_t)b*gridDim.x + blockIdx.x)*16 + tid] = sacc[tid];
}

// ---------------- final GN3 + lrelu + transpose ------------------------------
__global__ void k_final(float* __restrict__ out) {
  __shared__ float t[32][33];
  int b = blockIdx.z, c0 = blockIdx.y*32, n0 = blockIdx.x*32;
  int tx = threadIdx.x, ty = threadIdx.y;
  float scv = g_sc3[b*CC + c0 + tx], shv = g_sh3[b*CC + c0 + tx];
  #pragma unroll
  for (int i = 0; i < 4; i++) {
    int n = n0 + ty*4 + i;
    float x = g_aq[((size_t)b*NN + n)*CC + c0 + tx];
    float y = fmaf(scv, x, shv);
    t[tx][ty*4+i] = (y >= 0.f) ? y : 0.1f*y;
  }
  __syncthreads();
  #pragma unroll
  for (int i = 0; i < 4; i++) {
    int c = c0 + ty*4 + i;
    out[((size_t)b*CC + c)*NN + n0 + tx] = t[ty*4+i][tx];
  }
}

// ---------------- launch -----------------------------------------------------
extern "C" void kernel_launch(void* const* d_in, const int* in_sizes, int n_in,
                              void* d_out, int out_size) {
  const float* xyz    = (const float*)d_in[0];
  const float* feat   = (const float*)d_in[1];
  const float* pre_w  = (const float*)d_in[2];
  const float* pre_b  = (const float*)d_in[3];
  const float* wq_w   = (const float*)d_in[4];
  const float* wq_b   = (const float*)d_in[5];
  const float* wk_w   = (const float*)d_in[6];
  const float* wk_b   = (const float*)d_in[7];
  const float* wv_w   = (const float*)d_in[8];
  const float* wv_b   = (const float*)d_in[9];
  const float* pos1_w = (const float*)d_in[10];
  const float* pos1_b = (const float*)d_in[11];
  const float* pos1_g = (const float*)d_in[12];
  const float* pos1_be= (const float*)d_in[13];
  const float* att1_b = (const float*)d_in[17];
  const float* att1_g = (const float*)d_in[18];
  const float* att1_be= (const float*)d_in[19];
  const float* att2_w = (const float*)d_in[20];
  const float* att2_b = (const float*)d_in[21];
  const float* post_w = (const float*)d_in[22];
  const float* post_b = (const float*)d_in[23];
  const float* post_g = (const float*)d_in[24];
  const float* post_be= (const float*)d_in[25];
  float* out = (float*)d_out;

  const int SMEMC = (CC*129 + 2*CC*20 + 16) * 4;
  const int SMEMA = (CC*WP + CC*XP + 128 + 32 + 16) * 4;
  cudaFuncSetAttribute(k_conv_pm,  cudaFuncAttributeMaxDynamicSharedMemorySize, SMEMC);
  cudaFuncSetAttribute(k_conv_post,cudaFuncAttributeMaxDynamicSharedMemorySize, SMEMC);
  cudaFuncSetAttribute(k_att1,     cudaFuncAttributeMaxDynamicSharedMemorySize, SMEMA);
  cudaFuncSetAttribute(k_att2,     cudaFuncAttributeMaxDynamicSharedMemorySize, SMEMA);

  void *p_nf, *p_aq, *p_ak, *p_v, *p_y5, *p_Wq2, *p_Wk2;
  cudaGetSymbolAddress(&p_nf,  g_nf);
  cudaGetSymbolAddress(&p_aq,  g_aq);
  cudaGetSymbolAddress(&p_ak,  g_ak);
  cudaGetSymbolAddress(&p_v,   g_v);
  cudaGetSymbolAddress(&p_y5,  g_y5);
  cudaGetSymbolAddress(&p_Wq2, g_Wq2);
  cudaGetSymbolAddress(&p_Wk2, g_Wk2);

  k_knn<<<dim3(NN/8, BB), 256>>>(xyz);
  k_pre<<<dim3(NN/32, BB), 256>>>(feat, pre_w, pre_b);
  k_combine<<<4, 256>>>((const float*)d_in[16], wq_w, wk_w, (const float*)d_in[14],
                        att1_b, wq_b, wk_b, (const float*)d_in[15]);
  k_gn1<<<1024, 256>>>(xyz, pos1_w, pos1_b);
  k_reduce<<<2, 256>>>(0, 512, 1.f/2097152.f, pos1_g, pos1_be);
  k_conv_pm<<<dim3(128, BB), 256, SMEMC>>>((const float*)p_nf, (const float*)p_Wq2, att1_b, (float*)p_aq);
  k_conv_pm<<<dim3(128, BB), 256, SMEMC>>>((const float*)p_nf, (const float*)p_Wk2, att1_b, (float*)p_ak);
  k_conv_pm<<<dim3(128, BB), 256, SMEMC>>>((const float*)p_nf, wv_w, wv_b, (float*)p_v);
  k_att1<<<dim3(512, BB), 256, SMEMA>>>(xyz, pos1_w, pos1_b);
  k_reduce<<<2, 256>>>(1, 512, 1.f/2097152.f, att1_g, att1_be);
  k_att2<<<dim3(512, BB), 256, SMEMA>>>(att2_w, att2_b);
  k_conv_post<<<dim3(128, BB), 256, SMEMC>>>((const float*)p_y5, post_w, post_b, (float*)p_aq);
  k_reduce<<<2, 256>>>(2, 128, 1.f/131072.f, post_g, post_be);
  k_final<<<dim3(NN/32, CC/32, BB), dim3(32, 8)>>>(out);
}

// round 9
// speedup vs baseline: 1.2484x; 1.0075x over previous
#include <cuda_runtime.h>
#include <cuda_bf16.h>
#include <mma.h>
#include <math.h>
#include <stdint.h>

#define BB 2
#define NN 8192
#define CIN 64
#define CC 128
#define KK 16
#define EPSV 1e-5f

__device__ int   g_idx[BB*NN*KK];
__device__ float g_nf [(size_t)BB*NN*CC];
__device__ float g_aq [(size_t)BB*NN*CC];
__device__ float g_ak [(size_t)BB*NN*CC];
__device__ float g_v  [(size_t)BB*NN*CC];
__device__ float g_y5 [(size_t)BB*NN*CC];
__device__ float g_t1 [(size_t)BB*NN*KK*CC];
__device__ float g_M  [CC*CC];
__device__ float g_Wq2[CC*CC];
__device__ float g_Wk2[CC*CC];
__device__ float g_ccv[CC];
__device__ float g_part1[1024*16];
__device__ float g_part2[2048*16];
__device__ float g_part3[BB*128*16];
__device__ float g_sc1[BB*CC], g_sh1[BB*CC];
__device__ float g_sc2[BB*CC], g_sh2[BB*CC];
__device__ float g_sc3[BB*CC], g_sh3[BB*CC];

// smem byte offsets for the wmma att kernels
#define PA 136              // bf16 pitch for A/B tiles
#define PD 132              // f32 pitch for D tile
#define OFF_CO  0           // 128 float4
#define OFF_REL 2048        // 128 float4
#define OFF_JSH 4096        // 128 int
#define OFF_SAC 4608        // 16 float
#define OFF_AH  8192
#define OFF_AL  (OFF_AH + 128*PA*2)     // 43008
#define OFF_BH  (OFF_AL + 128*PA*2)     // 77824
#define OFF_BL  (OFF_BH + 128*PA*2)     // 112640
#define OFF_D   (OFF_BL + 128*PA*2)     // 147456
#define SMT     (OFF_D + 128*PD*4)      // 215040

extern __shared__ float dsm[];

__device__ __forceinline__ void split2(float a, float b, unsigned &h, unsigned &l) {
  __nv_bfloat16 ha = __float2bfloat16_rn(a), hb = __float2bfloat16_rn(b);
  h = ((unsigned)__bfloat16_as_ushort(hb) << 16) | __bfloat16_as_ushort(ha);
  __nv_bfloat16 la = __float2bfloat16_rn(a - __bfloat162float(ha));
  __nv_bfloat16 lb = __float2bfloat16_rn(b - __bfloat162float(hb));
  l = ((unsigned)__bfloat16_as_ushort(lb) << 16) | __bfloat16_as_ushort(la);
}

// build hi/lo bf16 tile row from 8 fp32 values
#define SPLIT8(v, hi, lo) { \
  split2(v[0],v[1],hi.x,lo.x); split2(v[2],v[3],hi.y,lo.y); \
  split2(v[4],v[5],hi.z,lo.z); split2(v[6],v[7],hi.w,lo.w); }

// ---- wmma GEMM: D[128x128] = A[128x128] @ B^T, 3-term bf16 split ----------
__device__ __forceinline__ void wmma_gemm(char* smc, int warp) {
  using namespace nvcuda;
  const __nv_bfloat16* Ah = (const __nv_bfloat16*)(smc + OFF_AH);
  const __nv_bfloat16* Al = (const __nv_bfloat16*)(smc + OFF_AL);
  const __nv_bfloat16* Bh = (const __nv_bfloat16*)(smc + OFF_BH);
  const __nv_bfloat16* Bl = (const __nv_bfloat16*)(smc + OFF_BL);
  float* D = (float*)(smc + OFF_D);
  int rb = warp >> 1, ch = warp & 1;
  wmma::fragment<wmma::accumulator,16,16,16,float> acc[2][4];
  #pragma unroll
  for (int r = 0; r < 2; r++)
    #pragma unroll
    for (int n = 0; n < 4; n++) wmma::fill_fragment(acc[r][n], 0.f);
  #pragma unroll
  for (int k = 0; k < 8; k++) {
    wmma::fragment<wmma::matrix_a,16,16,16,__nv_bfloat16,wmma::row_major> ah[2], al[2];
    #pragma unroll
    for (int r = 0; r < 2; r++) {
      wmma::load_matrix_sync(ah[r], Ah + (rb*32 + r*16)*PA + k*16, PA);
      wmma::load_matrix_sync(al[r], Al + (rb*32 + r*16)*PA + k*16, PA);
    }
    #pragma unroll
    for (int n = 0; n < 4; n++) {
      wmma::fragment<wmma::matrix_b,16,16,16,__nv_bfloat16,wmma::col_major> bh, bl;
      wmma::load_matrix_sync(bh, Bh + (ch*64 + n*16)*PA + k*16, PA);
      wmma::load_matrix_sync(bl, Bl + (ch*64 + n*16)*PA + k*16, PA);
      #pragma unroll
      for (int r = 0; r < 2; r++) {
        wmma::mma_sync(acc[r][n], ah[r], bh, acc[r][n]);
        wmma::mma_sync(acc[r][n], ah[r], bl, acc[r][n]);
        wmma::mma_sync(acc[r][n], al[r], bh, acc[r][n]);
      }
    }
  }
  #pragma unroll
  for (int r = 0; r < 2; r++)
    #pragma unroll
    for (int n = 0; n < 4; n++)
      wmma::store_matrix_sync(D + (rb*32 + r*16)*PD + ch*64 + n*16, acc[r][n], PD, wmma::mem_row_major);
}

// build hi/lo weight tile: row co of W -> B[co][ci]
__device__ __forceinline__ void build_wtile(const float* __restrict__ W, char* smc, int tid) {
  int row = tid >> 1, half = tid & 1;
  const float* src = W + row*CC + half*64;
  __nv_bfloat16* bh = (__nv_bfloat16*)(smc + OFF_BH) + row*PA + half*64;
  __nv_bfloat16* bl = (__nv_bfloat16*)(smc + OFF_BL) + row*PA + half*64;
  #pragma unroll
  for (int cc = 0; cc < 8; cc++) {
    float v[8];
    float4 f0 = *(const float4*)(src + cc*8);
    float4 f1 = *(const float4*)(src + cc*8 + 4);
    v[0]=f0.x;v[1]=f0.y;v[2]=f0.z;v[3]=f0.w;v[4]=f1.x;v[5]=f1.y;v[6]=f1.z;v[7]=f1.w;
    uint4 hi, lo; SPLIT8(v, hi, lo);
    *(uint4*)(bh + cc*8) = hi;
    *(uint4*)(bl + cc*8) = lo;
  }
}

#define GSTEP16(wv, base) { \
  float4 x0=*(const float4*)((base));    float4 x1=*(const float4*)((base)+4); \
  float4 x2=*(const float4*)((base)+8);  float4 x3=*(const float4*)((base)+12); \
  acc[0]=fmaf(wv,x0.x,acc[0]);  acc[1]=fmaf(wv,x0.y,acc[1]); \
  acc[2]=fmaf(wv,x0.z,acc[2]);  acc[3]=fmaf(wv,x0.w,acc[3]); \
  acc[4]=fmaf(wv,x1.x,acc[4]);  acc[5]=fmaf(wv,x1.y,acc[5]); \
  acc[6]=fmaf(wv,x1.z,acc[6]);  acc[7]=fmaf(wv,x1.w,acc[7]); \
  acc[8]=fmaf(wv,x2.x,acc[8]);  acc[9]=fmaf(wv,x2.y,acc[9]); \
  acc[10]=fmaf(wv,x2.z,acc[10]);acc[11]=fmaf(wv,x2.w,acc[11]); \
  acc[12]=fmaf(wv,x3.x,acc[12]);acc[13]=fmaf(wv,x3.y,acc[13]); \
  acc[14]=fmaf(wv,x3.z,acc[14]);acc[15]=fmaf(wv,x3.w,acc[15]); }

// ---------------- kNN -------------------------------------------------------
__global__ void __launch_bounds__(256) k_knn(const float* __restrict__ xyz) {
  __shared__ float4 sp[1024];
  int b = blockIdx.y;
  int n = blockIdx.x * 8 + (threadIdx.x >> 5);
  int lane = threadIdx.x & 31;
  const float* xb = xyz + (size_t)b * 3 * NN;
  float qx = xb[n], qy = xb[NN + n], qz = xb[2 * NN + n];
  float qsq = __fadd_rn(__fadd_rn(__fmul_rn(qx,qx), __fmul_rn(qy,qy)), __fmul_rn(qz,qz));
  float bd[16]; int bi[16];
  #pragma unroll
  for (int i = 0; i < 16; i++) { bd[i] = 3.4e38f; bi[i] = 0; }
  float worstv = 3.4e38f; int worsts = 0;
  for (int t0 = 0; t0 < NN; t0 += 1024) {
    __syncthreads();
    for (int e = threadIdx.x; e < 1024; e += 256) {
      float x = xb[t0+e], y = xb[NN+t0+e], z = xb[2*NN+t0+e];
      float sq = __fadd_rn(__fadd_rn(__fmul_rn(x,x), __fmul_rn(y,y)), __fmul_rn(z,z));
      sp[e] = make_float4(x, y, z, sq);
    }
    __syncthreads();
    for (int j = lane; j < 1024; j += 32) {
      float4 c = sp[j];
      float inner = __fadd_rn(__fadd_rn(__fmul_rn(qx,c.x), __fmul_rn(qy,c.y)), __fmul_rn(qz,c.z));
      float d2 = __fsub_rn(__fadd_rn(qsq, c.w), __fmul_rn(2.0f, inner));
      if (d2 < worstv) {
        int ci = t0 + j;
        #pragma unroll
        for (int i = 0; i < 16; i++) if (i == worsts) { bd[i] = d2; bi[i] = ci; }
        worstv = bd[0]; worsts = 0;
        #pragma unroll
        for (int i = 1; i < 16; i++) if (bd[i] > worstv) { worstv = bd[i]; worsts = i; }
      }
    }
  }
  unsigned used = 0;
  int* outp = g_idx + ((size_t)b * NN + n) * KK;
  for (int r = 0; r < 16; r++) {
    float mv = 3.4e38f; int mi = -1, ms = 0;
    #pragma unroll
    for (int i = 0; i < 16; i++)
      if (!((used >> i) & 1) && bd[i] < mv) { mv = bd[i]; mi = bi[i]; ms = i; }
    float bv = mv; int bidx = mi; int bl = lane;
    #pragma unroll
    for (int off = 16; off >= 1; off >>= 1) {
      float ov = __shfl_xor_sync(0xffffffffu, bv, off);
      int   oi = __shfl_xor_sync(0xffffffffu, bidx, off);
      int   ol = __shfl_xor_sync(0xffffffffu, bl, off);
      if (ov < bv || (ov == bv && ol < bl)) { bv = ov; bidx = oi; bl = ol; }
    }
    if (lane == bl) used |= 1u << ms;
    if (lane == 0) outp[r] = bidx;
  }
}

// ---------------- pre conv --------------------------------------------------
__global__ void __launch_bounds__(256) k_pre(const float* __restrict__ feat,
                                             const float* __restrict__ W,
                                             const float* __restrict__ bias) {
  __shared__ float wr[CC*65];
  __shared__ float buf[2*CIN*20];
  int tid = threadIdx.x, grp = tid >> 7, co = tid & 127;
  for (int e = tid; e < CC*CIN; e += 256) wr[(e>>6)*65 + (e&63)] = W[e];
  int b = blockIdx.y;
  int n0 = blockIdx.x*32 + grp*16;
  const float* fb = feat + (size_t)b * CIN * NN;
  for (int e = tid; e < 2*CIN*16; e += 256) {
    int g2 = e >> 10, ci = (e >> 4) & 63, p = e & 15;
    buf[g2*(CIN*20) + ci*20 + p] = fb[(size_t)ci*NN + blockIdx.x*32 + g2*16 + p];
  }
  __syncthreads();
  float* gb = buf + grp*(CIN*20);
  float acc[16]; float bv = bias[co];
  #pragma unroll
  for (int p = 0; p < 16; p++) acc[p] = bv;
  #pragma unroll 4
  for (int ci = 0; ci < CIN; ci++) { float w = wr[co*65+ci]; GSTEP16(w, gb + ci*20); }
  float* yb = g_nf + ((size_t)b*NN + n0) * CC;
  #pragma unroll
  for (int p = 0; p < 16; p++) yb[(size_t)p*CC + co] = acc[p];
}

// ---------------- weight folding --------------------------------------------
__global__ void k_combine(const float* __restrict__ A1, const float* __restrict__ Wq,
                          const float* __restrict__ Wk, const float* __restrict__ W2,
                          const float* __restrict__ a1b, const float* __restrict__ qb,
                          const float* __restrict__ kb, const float* __restrict__ p2b) {
  int z = blockIdx.x;
  if (z < 3) {
    const float* X = (z==0) ? Wq : ((z==1) ? Wk : W2);
    float* O = (z==0) ? g_Wq2 : ((z==1) ? g_Wk2 : g_M);
    for (int e = threadIdx.x; e < CC*CC; e += 256) {
      int o = e >> 7, c = e & 127;
      float s0=0.f, s1=0.f;
      for (int j = 0; j < CC; j += 2) {
        s0 = fmaf(A1[o*CC+j],   X[j*CC+c],     s0);
        s1 = fmaf(A1[o*CC+j+1], X[(j+1)*CC+c], s1);
      }
      O[e] = s0 + s1;
    }
  } else {
    for (int c = threadIdx.x; c < CC; c += 256) {
      float s = a1b[c];
      for (int j = 0; j < CC; j++) s = fmaf(A1[c*CC+j], qb[j]-kb[j]+p2b[j], s);
      g_ccv[c] = s;
    }
  }
}

// ---------------- GN1 stats -------------------------------------------------
__global__ void __launch_bounds__(256) k_gn1(const float* __restrict__ xyz,
                                             const float* __restrict__ p1w,
                                             const float* __restrict__ p1b) {
  __shared__ float sw[CC*4];
  __shared__ float sacc[16];
  int tid = threadIdx.x, lane = tid & 31;
  for (int e = tid; e < CC*3; e += 256) sw[e] = p1w[e];
  for (int e = tid; e < CC; e += 256) sw[CC*3+e] = p1b[e];
  if (tid < 16) sacc[tid] = 0.f;
  __syncthreads();
  size_t r = (size_t)blockIdx.x*256 + tid;
  int b = (int)(r >> 17);
  int n = (int)((r >> 4) & 8191);
  int j = g_idx[r];
  const float* xb = xyz + (size_t)b*3*NN;
  float rx = xb[j]-xb[n], ry = xb[NN+j]-xb[NN+n], rz = xb[2*NN+j]-xb[2*NN+n];
  #pragma unroll
  for (int g = 0; g < 8; g++) {
    float s = 0.f, ss = 0.f;
    #pragma unroll
    for (int cc = 0; cc < 16; cc++) {
      int c = g*16 + cc;
      float y = fmaf(sw[c*3], rx, fmaf(sw[c*3+1], ry, fmaf(sw[c*3+2], rz, sw[CC*3+c])));
      s += y; ss = fmaf(y, y, ss);
    }
    #pragma unroll
    for (int off = 16; off >= 1; off >>= 1) {
      s  += __shfl_down_sync(0xffffffffu, s, off);
      ss += __shfl_down_sync(0xffffffffu, ss, off);
    }
    if (lane == 0) { atomicAdd(&sacc[g], s); atomicAdd(&sacc[8+g], ss); }
  }
  __syncthreads();
  if (tid < 16) g_part1[blockIdx.x*16 + tid] = sacc[tid];
}

// ---------------- stats reduce ----------------------------------------------
__global__ void k_reduce(int which, int nblkb, float invcnt,
                         const float* __restrict__ gamma, const float* __restrict__ beta) {
  const float* P = (which==0) ? g_part1 : ((which==1) ? g_part2 : g_part3);
  float* sc = (which==0) ? g_sc1 : ((which==1) ? g_sc2 : g_sc3);
  float* sh = (which==0) ? g_sh1 : ((which==1) ? g_sh2 : g_sh3);
  int b = blockIdx.x, tid = threadIdx.x;
  int s = tid & 15, grp = tid >> 4;
  double acc = 0.0;
  for (int blk = grp; blk < nblkb; blk += 16)
    acc += (double)P[((size_t)b*nblkb + blk)*16 + s];
  __shared__ double rr[16][17];
  __shared__ double fin[16];
  rr[grp][s] = acc;
  __syncthreads();
  if (tid < 16) { double t = 0.0; for (int i = 0; i < 16; i++) t += rr[i][tid]; fin[tid] = t; }
  __syncthreads();
  if (tid < CC) {
    int g8 = tid >> 4;
    double mean = fin[g8] * (double)invcnt;
    double var  = fin[8+g8] * (double)invcnt - mean*mean;
    float rstd = rsqrtf((float)var + EPSV);
    float scv = gamma[tid] * rstd;
    sc[b*CC+tid] = scv;
    sh[b*CC+tid] = beta[tid] - (float)mean * scv;
  }
}

// ---------------- conv (FFMA, 2 tiles/block) --------------------------------
__global__ void __launch_bounds__(256) k_conv_pm(const float* __restrict__ X,
                                                 const float* __restrict__ W,
                                                 const float* __restrict__ bias,
                                                 float* __restrict__ Y) {
  float* wr = dsm;
  float* gb = dsm + CC*129;
  int tid = threadIdx.x, grp = tid >> 7, co = tid & 127;
  int b = blockIdx.y;
  for (int e = tid; e < CC*CC; e += 256) wr[(e>>7)*129 + (e&127)] = W[e];
  float bv = bias[co];
  float* g = gb + grp*(CC*20);
  for (int it = 0; it < 2; it++) {
    size_t r0 = (size_t)b*NN + (size_t)(blockIdx.x*2 + it)*32 + grp*16;
    __syncthreads();
    #pragma unroll
    for (int p = 0; p < 16; p++) g[co*20+p] = X[(r0+p)*CC + co];
    __syncthreads();
    float acc[16];
    #pragma unroll
    for (int p = 0; p < 16; p++) acc[p] = bv;
    #pragma unroll 4
    for (int ci = 0; ci < CC; ci++) { float w = wr[co*129+ci]; GSTEP16(w, g + ci*20); }
    #pragma unroll
    for (int p = 0; p < 16; p++) Y[(r0+p)*CC + co] = acc[p];
  }
}

// ---------------- att1 wmma kernel ------------------------------------------
__global__ void __launch_bounds__(256, 1) k_att1_w(const float* __restrict__ xyz,
                                                   const float* __restrict__ p1w,
                                                   const float* __restrict__ p1b) {
  char* smc = (char*)dsm;
  int tid = threadIdx.x, b = blockIdx.y;
  int warp = tid >> 5, lane = tid & 31;
  if (tid < 128) {
    float s1 = g_sc1[b*CC+tid], h1 = g_sh1[b*CC+tid];
    ((float4*)(smc+OFF_CO))[tid] = make_float4(s1*p1w[tid*3], s1*p1w[tid*3+1],
                                               s1*p1w[tid*3+2], fmaf(s1, p1b[tid], h1));
  }
  build_wtile(g_M, smc, tid);
  const float* xb = xyz + (size_t)b*3*NN;
  int row = tid >> 1, half = tid & 1;
  int sub = warp & 3, cb = (warp >> 2)*64;
  int er = sub*32 + lane;
  __nv_bfloat16* Ahp = (__nv_bfloat16*)(smc+OFF_AH) + row*PA + half*64;
  __nv_bfloat16* Alp = (__nv_bfloat16*)(smc+OFF_AL) + row*PA + half*64;
  const float* Drow = (const float*)(smc+OFF_D) + (size_t)er*PD + cb;
  for (int tl = blockIdx.x; tl < 1024; tl += gridDim.x) {
    int n0 = tl*8;
    size_t r0 = ((size_t)b*NN + n0)*16;
    __syncthreads();
    if (tid < 128) {
      int j = g_idx[r0 + tid];
      ((int*)(smc+OFF_JSH))[tid] = j;
      int nq = n0 + (tid >> 4);
      float4 rr;
      rr.x = xb[j]-xb[nq]; rr.y = xb[NN+j]-xb[NN+nq]; rr.z = xb[2*NN+j]-xb[2*NN+nq]; rr.w = 0.f;
      ((float4*)(smc+OFF_REL))[tid] = rr;
    }
    if (tid < 16) ((float*)(smc+OFF_SAC))[tid] = 0.f;
    __syncthreads();
    float4 rl = ((float4*)(smc+OFF_REL))[row];
    const float4* co4 = (const float4*)(smc+OFF_CO) + half*64;
    #pragma unroll
    for (int cc = 0; cc < 8; cc++) {
      float v[8];
      #pragma unroll
      for (int i = 0; i < 8; i++) {
        float4 c4 = co4[cc*8+i];
        float y = fmaf(c4.x, rl.x, fmaf(c4.y, rl.y, fmaf(c4.z, rl.z, c4.w)));
        v[i] = (y >= 0.f) ? y : 0.1f*y;
      }
      uint4 hi, lo; SPLIT8(v, hi, lo);
      *(uint4*)(Ahp + cc*8) = hi;
      *(uint4*)(Alp + cc*8) = lo;
    }
    __syncthreads();
    wmma_gemm(smc, warp);
    __syncthreads();
    int nq = n0 + (er >> 4), j = ((int*)(smc+OFF_JSH))[er];
    const float4* aqp = (const float4*)(g_aq + ((size_t)b*NN + nq)*CC + cb);
    const float4* akp = (const float4*)(g_ak + ((size_t)b*NN + j)*CC + cb);
    const float4* cvp = (const float4*)(g_ccv + cb);
    float4* op = (float4*)(g_t1 + (r0 + er)*CC + cb);
    float ts[4] = {0,0,0,0}, tss[4] = {0,0,0,0};
    #pragma unroll
    for (int q = 0; q < 16; q++) {
      float4 aq = aqp[q], ak = akp[q], cv = cvp[q], vv;
      vv.x = Drow[q*4+0] + cv.x + aq.x - ak.x;
      vv.y = Drow[q*4+1] + cv.y + aq.y - ak.y;
      vv.z = Drow[q*4+2] + cv.z + aq.z - ak.z;
      vv.w = Drow[q*4+3] + cv.w + aq.w - ak.w;
      op[q] = vv;
      int g = q >> 2;
      ts[g] += vv.x + vv.y + vv.z + vv.w;
      tss[g] = fmaf(vv.x,vv.x,fmaf(vv.y,vv.y,fmaf(vv.z,vv.z,fmaf(vv.w,vv.w,tss[g]))));
    }
    #pragma unroll
    for (int g = 0; g < 4; g++)
      #pragma unroll
      for (int off = 16; off >= 1; off >>= 1) {
        ts[g]  += __shfl_down_sync(0xffffffffu, ts[g], off);
        tss[g] += __shfl_down_sync(0xffffffffu, tss[g], off);
      }
    if (lane == 0) {
      float* sa = (float*)(smc+OFF_SAC);
      #pragma unroll
      for (int g = 0; g < 4; g++) {
        atomicAdd(&sa[cb/16 + g], ts[g]);
        atomicAdd(&sa[8 + cb/16 + g], tss[g]);
      }
    }
    __syncthreads();
    if (tid < 16) g_part2[((size_t)b*1024 + tl)*16 + tid] = ((float*)(smc+OFF_SAC))[tid];
  }
}

// ---------------- att2 wmma kernel (softmax + V-agg + residual) -------------
__global__ void __launch_bounds__(256, 1) k_att2_w(const float* __restrict__ W) {
  char* smc = (char*)dsm;
  int tid = threadIdx.x, b = blockIdx.y;
  int warp = tid >> 5, lane = tid & 31;
  if (tid < 128)
    ((float2*)(smc+OFF_CO))[tid] = make_float2(g_sc2[b*CC+tid], g_sh2[b*CC+tid]);
  build_wtile(W, smc, tid);
  int row = tid >> 1, half = tid & 1;
  int sub = warp & 3, cb = (warp >> 2)*64;
  int er = sub*32 + lane, kk = er & 15;
  __nv_bfloat16* Ahp = (__nv_bfloat16*)(smc+OFF_AH) + row*PA + half*64;
  __nv_bfloat16* Alp = (__nv_bfloat16*)(smc+OFF_AL) + row*PA + half*64;
  const float* Drow = (const float*)(smc+OFF_D) + (size_t)er*PD + cb;
  for (int tl = blockIdx.x; tl < 1024; tl += gridDim.x) {
    int n0 = tl*8;
    size_t r0 = ((size_t)b*NN + n0)*16;
    __syncthreads();
    if (tid < 128) ((int*)(smc+OFF_JSH))[tid] = g_idx[r0 + tid];
    {
      const float4* tp = (const float4*)(g_t1 + (r0 + row)*CC + half*64);
      const float2* c2 = (const float2*)(smc+OFF_CO) + half*64;
      #pragma unroll
      for (int cc = 0; cc < 8; cc++) {
        float4 f0 = tp[cc*2], f1 = tp[cc*2+1];
        float v[8] = {f0.x,f0.y,f0.z,f0.w,f1.x,f1.y,f1.z,f1.w};
        #pragma unroll
        for (int i = 0; i < 8; i++) {
          float2 c = c2[cc*8+i];
          float y = fmaf(c.x, v[i], c.y);
          v[i] = (y >= 0.f) ? y : 0.1f*y;
        }
        uint4 hi, lo; SPLIT8(v, hi, lo);
        *(uint4*)(Ahp + cc*8) = hi;
        *(uint4*)(Alp + cc*8) = lo;
      }
    }
    __syncthreads();
    wmma_gemm(smc, warp);
    __syncthreads();
    float a[64];
    #pragma unroll
    for (int q = 0; q < 64; q++) {
      float x = Drow[q];
      float m = x;
      #pragma unroll
      for (int off = 8; off >= 1; off >>= 1) m = fmaxf(m, __shfl_xor_sync(0xffffffffu, m, off, 16));
      float e = __expf(x - m);
      float s = e;
      #pragma unroll
      for (int off = 8; off >= 1; off >>= 1) s += __shfl_xor_sync(0xffffffffu, s, off, 16);
      a[q] = e / s;
    }
    int nq = n0 + (er >> 4), j = ((int*)(smc+OFF_JSH))[er];
    const float4* vp = (const float4*)(g_v + ((size_t)b*NN + j)*CC + cb);
    const float4* np = (const float4*)(g_nf + ((size_t)b*NN + nq)*CC + cb);
    float4* yp = (float4*)(g_y5 + ((size_t)b*NN + nq)*CC + cb);
    #pragma unroll
    for (int q4 = 0; q4 < 16; q4++) {
      float4 vv = vp[q4], oo;
      oo.x = a[q4*4+0]*vv.x; oo.y = a[q4*4+1]*vv.y;
      oo.z = a[q4*4+2]*vv.z; oo.w = a[q4*4+3]*vv.w;
      #pragma unroll
      for (int off = 8; off >= 1; off >>= 1) {
        oo.x += __shfl_xor_sync(0xffffffffu, oo.x, off, 16);
        oo.y += __shfl_xor_sync(0xffffffffu, oo.y, off, 16);
        oo.z += __shfl_xor_sync(0xffffffffu, oo.z, off, 16);
        oo.w += __shfl_xor_sync(0xffffffffu, oo.w, off, 16);
      }
      if (kk == 0) {
        float4 nf = np[q4], r;
        r.x = oo.x + nf.x; r.y = oo.y + nf.y; r.z = oo.z + nf.z; r.w = oo.w + nf.w;
        yp[q4] = r;
      }
    }
  }
}

// ---------------- post conv + stats -----------------------------------------
__global__ void __launch_bounds__(256) k_conv_post(const float* __restrict__ X,
                                                   const float* __restrict__ W,
                                                   const float* __restrict__ bias,
                                                   float* __restrict__ Y) {
  float* wr = dsm;
  float* gb = dsm + CC*129;
  float* sacc = gb + 2*CC*20;
  int tid = threadIdx.x, grp = tid >> 7, co = tid & 127, lane = tid & 31;
  int b = blockIdx.y;
  for (int e = tid; e < CC*CC; e += 256) wr[(e>>7)*129 + (e&127)] = W[e];
  if (tid < 16) sacc[tid] = 0.f;
  float bv = bias[co];
  float* g = gb + grp*(CC*20);
  float ts = 0.f, tss = 0.f;
  for (int it = 0; it < 2; it++) {
    size_t r0 = (size_t)b*NN + (size_t)(blockIdx.x*2 + it)*32 + grp*16;
    __syncthreads();
    #pragma unroll
    for (int p = 0; p < 16; p++) g[co*20+p] = X[(r0+p)*CC + co];
    __syncthreads();
    float acc[16];
    #pragma unroll
    for (int p = 0; p < 16; p++) acc[p] = bv;
    #pragma unroll 4
    for (int ci = 0; ci < CC; ci++) { float w = wr[co*129+ci]; GSTEP16(w, g + ci*20); }
    #pragma unroll
    for (int p = 0; p < 16; p++) { Y[(r0+p)*CC + co] = acc[p]; ts += acc[p]; tss = fmaf(acc[p],acc[p],tss); }
  }
  #pragma unroll
  for (int off = 8; off >= 1; off >>= 1) {
    ts  += __shfl_down_sync(0xffffffffu, ts, off, 16);
    tss += __shfl_down_sync(0xffffffffu, tss, off, 16);
  }
  if ((lane & 15) == 0) {
    int cgg = co >> 4;
    atomicAdd(&sacc[cgg], ts); atomicAdd(&sacc[8+cgg], tss);
  }
  __syncthreads();
  if (tid < 16) g_part3[((size_t)b*gridDim.x + blockIdx.x)*16 + tid] = sacc[tid];
}

// ---------------- final GN3 + lrelu + transpose -----------------------------
__global__ void k_final(float* __restrict__ out) {
  __shared__ float t[32][33];
  int b = blockIdx.z, c0 = blockIdx.y*32, n0 = blockIdx.x*32;
  int tx = threadIdx.x, ty = threadIdx.y;
  float scv = g_sc3[b*CC + c0 + tx], shv = g_sh3[b*CC + c0 + tx];
  #pragma unroll
  for (int i = 0; i < 4; i++) {
    int n = n0 + ty*4 + i;
    float x = g_aq[((size_t)b*NN + n)*CC + c0 + tx];
    float y = fmaf(scv, x, shv);
    t[tx][ty*4+i] = (y >= 0.f) ? y : 0.1f*y;
  }
  __syncthreads();
  #pragma unroll
  for (int i = 0; i < 4; i++) {
    int c = c0 + ty*4 + i;
    out[((size_t)b*CC + c)*NN + n0 + tx] = t[ty*4+i][tx];
  }
}

// ---------------- launch ----------------------------------------------------
extern "C" void kernel_launch(void* const* d_in, const int* in_sizes, int n_in,
                              void* d_out, int out_size) {
  const float* xyz    = (const float*)d_in[0];
  const float* feat   = (const float*)d_in[1];
  const float* pre_w  = (const float*)d_in[2];
  const float* pre_b  = (const float*)d_in[3];
  const float* wq_w   = (const float*)d_in[4];
  const float* wq_b   = (const float*)d_in[5];
  const float* wk_w   = (const float*)d_in[6];
  const float* wk_b   = (const float*)d_in[7];
  const float* wv_w   = (const float*)d_in[8];
  const float* wv_b   = (const float*)d_in[9];
  const float* pos1_w = (const float*)d_in[10];
  const float* pos1_b = (const float*)d_in[11];
  const float* pos1_g = (const float*)d_in[12];
  const float* pos1_be= (const float*)d_in[13];
  const float* att1_b = (const float*)d_in[17];
  const float* att1_g = (const float*)d_in[18];
  const float* att1_be= (const float*)d_in[19];
  const float* att2_w = (const float*)d_in[20];
  const float* post_w = (const float*)d_in[22];
  const float* post_b = (const float*)d_in[23];
  const float* post_g = (const float*)d_in[24];
  const float* post_be= (const float*)d_in[25];
  float* out = (float*)d_out;

  const int SMEMC = (CC*129 + 2*CC*20 + 16) * 4;
  cudaFuncSetAttribute(k_conv_pm,  cudaFuncAttributeMaxDynamicSharedMemorySize, SMEMC);
  cudaFuncSetAttribute(k_conv_post,cudaFuncAttributeMaxDynamicSharedMemorySize, SMEMC);
  cudaFuncSetAttribute(k_att1_w,   cudaFuncAttributeMaxDynamicSharedMemorySize, SMT);
  cudaFuncSetAttribute(k_att2_w,   cudaFuncAttributeMaxDynamicSharedMemorySize, SMT);

  void *p_nf, *p_aq, *p_ak, *p_v, *p_y5, *p_Wq2, *p_Wk2;
  cudaGetSymbolAddress(&p_nf,  g_nf);
  cudaGetSymbolAddress(&p_aq,  g_aq);
  cudaGetSymbolAddress(&p_ak,  g_ak);
  cudaGetSymbolAddress(&p_v,   g_v);
  cudaGetSymbolAddress(&p_y5,  g_y5);
  cudaGetSymbolAddress(&p_Wq2, g_Wq2);
  cudaGetSymbolAddress(&p_Wk2, g_Wk2);

  k_knn<<<dim3(NN/8, BB), 256>>>(xyz);
  k_pre<<<dim3(NN/32, BB), 256>>>(feat, pre_w, pre_b);
  k_combine<<<4, 256>>>((const float*)d_in[16], wq_w, wk_w, (const float*)d_in[14],
                        att1_b, wq_b, wk_b, (const float*)d_in[15]);
  k_gn1<<<1024, 256>>>(xyz, pos1_w, pos1_b);
  k_reduce<<<2, 256>>>(0, 512, 1.f/2097152.f, pos1_g, pos1_be);
  k_conv_pm<<<dim3(128, BB), 256, SMEMC>>>((const float*)p_nf, (const float*)p_Wq2, att1_b, (float*)p_aq);
  k_conv_pm<<<dim3(128, BB), 256, SMEMC>>>((const float*)p_nf, (const float*)p_Wk2, att1_b, (float*)p_ak);
  k_conv_pm<<<dim3(128, BB), 256, SMEMC>>>((const float*)p_nf, wv_w, wv_b, (float*)p_v);
  k_att1_w<<<dim3(74, BB), 256, SMT>>>(xyz, pos1_w, pos1_b);
  k_reduce<<<2, 256>>>(1, 1024, 1.f/2097152.f, att1_g, att1_be);
  k_att2_w<<<dim3(74, BB), 256, SMT>>>(att2_w);
  k_conv_post<<<dim3(128, BB), 256, SMEMC>>>((const float*)p_y5, post_w, post_b, (float*)p_aq);
  k_reduce<<<2, 256>>>(2, 128, 1.f/131072.f, post_g, post_be);
  k_final<<<dim3(NN/32, CC/32, BB), dim3(32, 8)>>>(out);
}

// round 11
// speedup vs baseline: 1.4101x; 1.1295x over previous
#include <cuda_runtime.h>
#include <cuda_bf16.h>
#include <mma.h>
#include <math.h>
#include <stdint.h>

#define BB 2
#define NN 8192
#define CIN 64
#define CC 128
#define KK 16
#define EPSV 1e-5f

__device__ int   g_idx[BB*NN*KK];
__device__ float g_nf [(size_t)BB*NN*CC];
__device__ float g_aq [(size_t)BB*NN*CC];
__device__ float g_ak [(size_t)BB*NN*CC];
__device__ float g_v  [(size_t)BB*NN*CC];
__device__ float g_y5 [(size_t)BB*NN*CC];
__device__ float g_t1 [(size_t)BB*NN*KK*CC];
__device__ float g_M  [CC*CC];
__device__ float g_Wq2[CC*CC];
__device__ float g_Wk2[CC*CC];
__device__ float g_ccv[CC];
__device__ float g_part1[1024*16];
__device__ float g_part2[2048*16];
__device__ float g_part3[BB*128*16];
__device__ float g_sc1[BB*CC], g_sh1[BB*CC];
__device__ float g_sc2[BB*CC], g_sh2[BB*CC];
__device__ float g_sc3[BB*CC], g_sh3[BB*CC];

// smem byte offsets for the wmma att kernels
#define PA 136              // bf16 pitch for A/B tiles
#define PD 132              // f32 pitch for D tile
#define OFF_CO  0           // 128 float4
#define OFF_REL 2048        // 128 float4
#define OFF_JSH 4096        // 128 int
#define OFF_SAC 4608        // 16 float
#define OFF_AH  8192
#define OFF_AL  (OFF_AH + 128*PA*2)     // 43008
#define OFF_BH  (OFF_AL + 128*PA*2)     // 77824
#define OFF_BL  (OFF_BH + 128*PA*2)     // 112640
#define OFF_D   (OFF_BL + 128*PA*2)     // 147456
#define SMT     (OFF_D + 128*PD*4)      // 215040

extern __shared__ float dsm[];

__device__ __forceinline__ void split2(float a, float b, unsigned &h, unsigned &l) {
  __nv_bfloat16 ha = __float2bfloat16_rn(a), hb = __float2bfloat16_rn(b);
  h = ((unsigned)__bfloat16_as_ushort(hb) << 16) | __bfloat16_as_ushort(ha);
  __nv_bfloat16 la = __float2bfloat16_rn(a - __bfloat162float(ha));
  __nv_bfloat16 lb = __float2bfloat16_rn(b - __bfloat162float(hb));
  l = ((unsigned)__bfloat16_as_ushort(lb) << 16) | __bfloat16_as_ushort(la);
}

#define SPLIT8(v, hi, lo) { \
  split2(v[0],v[1],hi.x,lo.x); split2(v[2],v[3],hi.y,lo.y); \
  split2(v[4],v[5],hi.z,lo.z); split2(v[6],v[7],hi.w,lo.w); }

// ---- wmma GEMM: D[128x128] = A[128x128] @ B^T, 3-term bf16 split ----------
__device__ __forceinline__ void wmma_gemm(char* smc, int warp) {
  using namespace nvcuda;
  const __nv_bfloat16* Ah = (const __nv_bfloat16*)(smc + OFF_AH);
  const __nv_bfloat16* Al = (const __nv_bfloat16*)(smc + OFF_AL);
  const __nv_bfloat16* Bh = (const __nv_bfloat16*)(smc + OFF_BH);
  const __nv_bfloat16* Bl = (const __nv_bfloat16*)(smc + OFF_BL);
  float* D = (float*)(smc + OFF_D);
  int rb = warp >> 1, ch = warp & 1;
  wmma::fragment<wmma::accumulator,16,16,16,float> acc[2][4];
  #pragma unroll
  for (int r = 0; r < 2; r++)
    #pragma unroll
    for (int n = 0; n < 4; n++) wmma::fill_fragment(acc[r][n], 0.f);
  #pragma unroll
  for (int k = 0; k < 8; k++) {
    wmma::fragment<wmma::matrix_a,16,16,16,__nv_bfloat16,wmma::row_major> ah[2], al[2];
    #pragma unroll
    for (int r = 0; r < 2; r++) {
      wmma::load_matrix_sync(ah[r], Ah + (rb*32 + r*16)*PA + k*16, PA);
      wmma::load_matrix_sync(al[r], Al + (rb*32 + r*16)*PA + k*16, PA);
    }
    #pragma unroll
    for (int n = 0; n < 4; n++) {
      wmma::fragment<wmma::matrix_b,16,16,16,__nv_bfloat16,wmma::col_major> bh, bl;
      wmma::load_matrix_sync(bh, Bh + (ch*64 + n*16)*PA + k*16, PA);
      wmma::load_matrix_sync(bl, Bl + (ch*64 + n*16)*PA + k*16, PA);
      #pragma unroll
      for (int r = 0; r < 2; r++) {
        wmma::mma_sync(acc[r][n], ah[r], bh, acc[r][n]);
        wmma::mma_sync(acc[r][n], ah[r], bl, acc[r][n]);
        wmma::mma_sync(acc[r][n], al[r], bh, acc[r][n]);
      }
    }
  }
  #pragma unroll
  for (int r = 0; r < 2; r++)
    #pragma unroll
    for (int n = 0; n < 4; n++)
      wmma::store_matrix_sync(D + (rb*32 + r*16)*PD + ch*64 + n*16, acc[r][n], PD, wmma::mem_row_major);
}

__device__ __forceinline__ void build_wtile(const float* __restrict__ W, char* smc, int tid) {
  int row = tid >> 1, half = tid & 1;
  const float* src = W + row*CC + half*64;
  __nv_bfloat16* bh = (__nv_bfloat16*)(smc + OFF_BH) + row*PA + half*64;
  __nv_bfloat16* bl = (__nv_bfloat16*)(smc + OFF_BL) + row*PA + half*64;
  #pragma unroll
  for (int cc = 0; cc < 8; cc++) {
    float v[8];
    float4 f0 = *(const float4*)(src + cc*8);
    float4 f1 = *(const float4*)(src + cc*8 + 4);
    v[0]=f0.x;v[1]=f0.y;v[2]=f0.z;v[3]=f0.w;v[4]=f1.x;v[5]=f1.y;v[6]=f1.z;v[7]=f1.w;
    uint4 hi, lo; SPLIT8(v, hi, lo);
    *(uint4*)(bh + cc*8) = hi;
    *(uint4*)(bl + cc*8) = lo;
  }
}

#define GSTEP16(wv, base) { \
  float4 x0=*(const float4*)((base));    float4 x1=*(const float4*)((base)+4); \
  float4 x2=*(const float4*)((base)+8);  float4 x3=*(const float4*)((base)+12); \
  acc[0]=fmaf(wv,x0.x,acc[0]);  acc[1]=fmaf(wv,x0.y,acc[1]); \
  acc[2]=fmaf(wv,x0.z,acc[2]);  acc[3]=fmaf(wv,x0.w,acc[3]); \
  acc[4]=fmaf(wv,x1.x,acc[4]);  acc[5]=fmaf(wv,x1.y,acc[5]); \
  acc[6]=fmaf(wv,x1.z,acc[6]);  acc[7]=fmaf(wv,x1.w,acc[7]); \
  acc[8]=fmaf(wv,x2.x,acc[8]);  acc[9]=fmaf(wv,x2.y,acc[9]); \
  acc[10]=fmaf(wv,x2.z,acc[10]);acc[11]=fmaf(wv,x2.w,acc[11]); \
  acc[12]=fmaf(wv,x3.x,acc[12]);acc[13]=fmaf(wv,x3.y,acc[13]); \
  acc[14]=fmaf(wv,x3.z,acc[14]);acc[15]=fmaf(wv,x3.w,acc[15]); }

// ---------------- kNN: THREAD per query (update prob decays as 16/j) --------
__global__ void __launch_bounds__(128) k_knn(const float* __restrict__ xyz) {
  __shared__ float4 sp[1024];
  int b = blockIdx.y;
  int n = blockIdx.x * 128 + threadIdx.x;
  const float* xb = xyz + (size_t)b * 3 * NN;
  float qx = xb[n], qy = xb[NN + n], qz = xb[2 * NN + n];
  float qsq = __fadd_rn(__fadd_rn(__fmul_rn(qx,qx), __fmul_rn(qy,qy)), __fmul_rn(qz,qz));
  float bd[16]; int bi[16];
  #pragma unroll
  for (int i = 0; i < 16; i++) { bd[i] = 3.4e38f; bi[i] = 0; }
  float worstv = 3.4e38f; int worsts = 0;
  for (int t0 = 0; t0 < NN; t0 += 1024) {
    __syncthreads();
    for (int e = threadIdx.x; e < 1024; e += 128) {
      float x = xb[t0+e], y = xb[NN+t0+e], z = xb[2*NN+t0+e];
      float sq = __fadd_rn(__fadd_rn(__fmul_rn(x,x), __fmul_rn(y,y)), __fmul_rn(z,z));
      sp[e] = make_float4(x, y, z, sq);
    }
    __syncthreads();
    for (int j = 0; j < 1024; j++) {
      float4 c = sp[j];
      float inner = __fadd_rn(__fadd_rn(__fmul_rn(qx,c.x), __fmul_rn(qy,c.y)), __fmul_rn(qz,c.z));
      float d2 = __fsub_rn(__fadd_rn(qsq, c.w), __fmul_rn(2.0f, inner));
      if (d2 < worstv) {
        int ci = t0 + j;
        #pragma unroll
        for (int i = 0; i < 16; i++) if (i == worsts) { bd[i] = d2; bi[i] = ci; }
        worstv = bd[0]; worsts = 0;
        #pragma unroll
        for (int i = 1; i < 16; i++) if (bd[i] > worstv) { worstv = bd[i]; worsts = i; }
      }
    }
  }
  // order of neighbors is irrelevant downstream (softmax/sum/GN are K-symmetric)
  int* outp = g_idx + ((size_t)b * NN + n) * KK;
  #pragma unroll
  for (int r = 0; r < 16; r++) outp[r] = bi[r];
}

// ---------------- pre conv --------------------------------------------------
__global__ void __launch_bounds__(256) k_pre(const float* __restrict__ feat,
                                             const float* __restrict__ W,
                                             const float* __restrict__ bias) {
  __shared__ float wr[CC*65];
  __shared__ float buf[2*CIN*20];
  int tid = threadIdx.x, grp = tid >> 7, co = tid & 127;
  for (int e = tid; e < CC*CIN; e += 256) wr[(e>>6)*65 + (e&63)] = W[e];
  int b = blockIdx.y;
  int n0 = blockIdx.x*32 + grp*16;
  const float* fb = feat + (size_t)b * CIN * NN;
  for (int e = tid; e < 2*CIN*16; e += 256) {
    int g2 = e >> 10, ci = (e >> 4) & 63, p = e & 15;
    buf[g2*(CIN*20) + ci*20 + p] = fb[(size_t)ci*NN + blockIdx.x*32 + g2*16 + p];
  }
  __syncthreads();
  float* gb = buf + grp*(CIN*20);
  float acc[16]; float bv = bias[co];
  #pragma unroll
  for (int p = 0; p < 16; p++) acc[p] = bv;
  #pragma unroll 4
  for (int ci = 0; ci < CIN; ci++) { float w = wr[co*65+ci]; GSTEP16(w, gb + ci*20); }
  float* yb = g_nf + ((size_t)b*NN + n0) * CC;
  #pragma unroll
  for (int p = 0; p < 16; p++) yb[(size_t)p*CC + co] = acc[p];
}

// ---------------- weight folding --------------------------------------------
__global__ void k_combine(const float* __restrict__ A1, const float* __restrict__ Wq,
                          const float* __restrict__ Wk, const float* __restrict__ W2,
                          const float* __restrict__ a1b, const float* __restrict__ qb,
                          const float* __restrict__ kb, const float* __restrict__ p2b) {
  int z = blockIdx.x;
  if (z < 3) {
    const float* X = (z==0) ? Wq : ((z==1) ? Wk : W2);
    float* O = (z==0) ? g_Wq2 : ((z==1) ? g_Wk2 : g_M);
    for (int e = threadIdx.x; e < CC*CC; e += 256) {
      int o = e >> 7, c = e & 127;
      float s0=0.f, s1=0.f;
      for (int j = 0; j < CC; j += 2) {
        s0 = fmaf(A1[o*CC+j],   X[j*CC+c],     s0);
        s1 = fmaf(A1[o*CC+j+1], X[(j+1)*CC+c], s1);
      }
      O[e] = s0 + s1;
    }
  } else {
    for (int c = threadIdx.x; c < CC; c += 256) {
      float s = a1b[c];
      for (int j = 0; j < CC; j++) s = fmaf(A1[c*CC+j], qb[j]-kb[j]+p2b[j], s);
      g_ccv[c] = s;
    }
  }
}

// ---------------- GN1 stats -------------------------------------------------
__global__ void __launch_bounds__(256) k_gn1(const float* __restrict__ xyz,
                                             const float* __restrict__ p1w,
                                             const float* __restrict__ p1b) {
  __shared__ float sw[CC*4];
  __shared__ float sacc[16];
  int tid = threadIdx.x, lane = tid & 31;
  for (int e = tid; e < CC*3; e += 256) sw[e] = p1w[e];
  for (int e = tid; e < CC; e += 256) sw[CC*3+e] = p1b[e];
  if (tid < 16) sacc[tid] = 0.f;
  __syncthreads();
  size_t r = (size_t)blockIdx.x*256 + tid;
  int b = (int)(r >> 17);
  int n = (int)((r >> 4) & 8191);
  int j = g_idx[r];
  const float* xb = xyz + (size_t)b*3*NN;
  float rx = xb[j]-xb[n], ry = xb[NN+j]-xb[NN+n], rz = xb[2*NN+j]-xb[2*NN+n];
  #pragma unroll
  for (int g = 0; g < 8; g++) {
    float s = 0.f, ss = 0.f;
    #pragma unroll
    for (int cc = 0; cc < 16; cc++) {
      int c = g*16 + cc;
      float y = fmaf(sw[c*3], rx, fmaf(sw[c*3+1], ry, fmaf(sw[c*3+2], rz, sw[CC*3+c])));
      s += y; ss = fmaf(y, y, ss);
    }
    #pragma unroll
    for (int off = 16; off >= 1; off >>= 1) {
      s  += __shfl_down_sync(0xffffffffu, s, off);
      ss += __shfl_down_sync(0xffffffffu, ss, off);
    }
    if (lane == 0) { atomicAdd(&sacc[g], s); atomicAdd(&sacc[8+g], ss); }
  }
  __syncthreads();
  if (tid < 16) g_part1[blockIdx.x*16 + tid] = sacc[tid];
}

// ---------------- stats reduce ----------------------------------------------
__global__ void k_reduce(int which, int nblkb, float invcnt,
                         const float* __restrict__ gamma, const float* __restrict__ beta) {
  const float* P = (which==0) ? g_part1 : ((which==1) ? g_part2 : g_part3);
  float* sc = (which==0) ? g_sc1 : ((which==1) ? g_sc2 : g_sc3);
  float* sh = (which==0) ? g_sh1 : ((which==1) ? g_sh2 : g_sh3);
  int b = blockIdx.x, tid = threadIdx.x;
  int s = tid & 15, grp = tid >> 4;
  double acc = 0.0;
  for (int blk = grp; blk < nblkb; blk += 16)
    acc += (double)P[((size_t)b*nblkb + blk)*16 + s];
  __shared__ double rr[16][17];
  __shared__ double fin[16];
  rr[grp][s] = acc;
  __syncthreads();
  if (tid < 16) { double t = 0.0; for (int i = 0; i < 16; i++) t += rr[i][tid]; fin[tid] = t; }
  __syncthreads();
  if (tid < CC) {
    int g8 = tid >> 4;
    double mean = fin[g8] * (double)invcnt;
    double var  = fin[8+g8] * (double)invcnt - mean*mean;
    float rstd = rsqrtf((float)var + EPSV);
    float scv = gamma[tid] * rstd;
    sc[b*CC+tid] = scv;
    sh[b*CC+tid] = beta[tid] - (float)mean * scv;
  }
}

// ------ QKV conv: one launch, blockIdx.z selects weight/bias/output ---------
__global__ void __launch_bounds__(256) k_convQKV(const float* __restrict__ Wv,
                                                 const float* __restrict__ a1b,
                                                 const float* __restrict__ vb) {
  float* wr = dsm;
  float* gb = dsm + CC*129;
  int tid = threadIdx.x, grp = tid >> 7, co = tid & 127;
  int b = blockIdx.y, z = blockIdx.z;
  const float* W = (z==0) ? g_Wq2 : ((z==1) ? g_Wk2 : Wv);
  const float* bias = (z==2) ? vb : a1b;
  float* Y = (z==0) ? g_aq : ((z==1) ? g_ak : g_v);
  for (int e = tid; e < CC*CC; e += 256) wr[(e>>7)*129 + (e&127)] = W[e];
  float bv = bias[co];
  float* g = gb + grp*(CC*20);
  for (int it = 0; it < 2; it++) {
    size_t r0 = (size_t)b*NN + (size_t)(blockIdx.x*2 + it)*32 + grp*16;
    __syncthreads();
    #pragma unroll
    for (int p = 0; p < 16; p++) g[co*20+p] = g_nf[(r0+p)*CC + co];
    __syncthreads();
    float acc[16];
    #pragma unroll
    for (int p = 0; p < 16; p++) acc[p] = bv;
    #pragma unroll 4
    for (int ci = 0; ci < CC; ci++) { float w = wr[co*129+ci]; GSTEP16(w, g + ci*20); }
    #pragma unroll
    for (int p = 0; p < 16; p++) Y[(r0+p)*CC + co] = acc[p];
  }
}

// ---------------- att1 wmma kernel ------------------------------------------
__global__ void __launch_bounds__(256, 1) k_att1_w(const float* __restrict__ xyz,
                                                   const float* __restrict__ p1w,
                                                   const float* __restrict__ p1b) {
  char* smc = (char*)dsm;
  int tid = threadIdx.x, b = blockIdx.y;
  int warp = tid >> 5, lane = tid & 31;
  if (tid < 128) {
    float s1 = g_sc1[b*CC+tid], h1 = g_sh1[b*CC+tid];
    ((float4*)(smc+OFF_CO))[tid] = make_float4(s1*p1w[tid*3], s1*p1w[tid*3+1],
                                               s1*p1w[tid*3+2], fmaf(s1, p1b[tid], h1));
  }
  build_wtile(g_M, smc, tid);
  const float* xb = xyz + (size_t)b*3*NN;
  int row = tid >> 1, half = tid & 1;
  int sub = warp & 3, cb = (warp >> 2)*64;
  int er = sub*32 + lane;
  __nv_bfloat16* Ahp = (__nv_bfloat16*)(smc+OFF_AH) + row*PA + half*64;
  __nv_bfloat16* Alp = (__nv_bfloat16*)(smc+OFF_AL) + row*PA + half*64;
  const float* Drow = (const float*)(smc+OFF_D) + (size_t)er*PD + cb;
  for (int tl = blockIdx.x; tl < 1024; tl += gridDim.x) {
    int n0 = tl*8;
    size_t r0 = ((size_t)b*NN + n0)*16;
    __syncthreads();
    if (tid < 128) {
      int j = g_idx[r0 + tid];
      ((int*)(smc+OFF_JSH))[tid] = j;
      int nq = n0 + (tid >> 4);
      float4 rr;
      rr.x = xb[j]-xb[nq]; rr.y = xb[NN+j]-xb[NN+nq]; rr.z = xb[2*NN+j]-xb[2*NN+nq]; rr.w = 0.f;
      ((float4*)(smc+OFF_REL))[tid] = rr;
    }
    if (tid < 16) ((float*)(smc+OFF_SAC))[tid] = 0.f;
    __syncthreads();
    float4 rl = ((float4*)(smc+OFF_REL))[row];
    const float4* co4 = (const float4*)(smc+OFF_CO) + half*64;
    #pragma unroll
    for (int cc = 0; cc < 8; cc++) {
      float v[8];
      #pragma unroll
      for (int i = 0; i < 8; i++) {
        float4 c4 = co4[cc*8+i];
        float y = fmaf(c4.x, rl.x, fmaf(c4.y, rl.y, fmaf(c4.z, rl.z, c4.w)));
        v[i] = (y >= 0.f) ? y : 0.1f*y;
      }
      uint4 hi, lo; SPLIT8(v, hi, lo);
      *(uint4*)(Ahp + cc*8) = hi;
      *(uint4*)(Alp + cc*8) = lo;
    }
    __syncthreads();
    wmma_gemm(smc, warp);
    __syncthreads();
    int nq = n0 + (er >> 4), j = ((int*)(smc+OFF_JSH))[er];
    const float4* aqp = (const float4*)(g_aq + ((size_t)b*NN + nq)*CC + cb);
    const float4* akp = (const float4*)(g_ak + ((size_t)b*NN + j)*CC + cb);
    const float4* cvp = (const float4*)(g_ccv + cb);
    float4* op = (float4*)(g_t1 + (r0 + er)*CC + cb);
    float ts[4] = {0,0,0,0}, tss[4] = {0,0,0,0};
    #pragma unroll
    for (int q = 0; q < 16; q++) {
      float4 aq = aqp[q], ak = akp[q], cv = cvp[q], vv;
      vv.x = Drow[q*4+0] + cv.x + aq.x - ak.x;
      vv.y = Drow[q*4+1] + cv.y + aq.y - ak.y;
      vv.z = Drow[q*4+2] + cv.z + aq.z - ak.z;
      vv.w = Drow[q*4+3] + cv.w + aq.w - ak.w;
      op[q] = vv;
      int g = q >> 2;
      ts[g] += vv.x + vv.y + vv.z + vv.w;
      tss[g] = fmaf(vv.x,vv.x,fmaf(vv.y,vv.y,fmaf(vv.z,vv.z,fmaf(vv.w,vv.w,tss[g]))));
    }
    #pragma unroll
    for (int g = 0; g < 4; g++)
      #pragma unroll
      for (int off = 16; off >= 1; off >>= 1) {
        ts[g]  += __shfl_down_sync(0xffffffffu, ts[g], off);
        tss[g] += __shfl_down_sync(0xffffffffu, tss[g], off);
      }
    if (lane == 0) {
      float* sa = (float*)(smc+OFF_SAC);
      #pragma unroll
      for (int g = 0; g < 4; g++) {
        atomicAdd(&sa[cb/16 + g], ts[g]);
        atomicAdd(&sa[8 + cb/16 + g], tss[g]);
      }
    }
    __syncthreads();
    if (tid < 16) g_part2[((size_t)b*1024 + tl)*16 + tid] = ((float*)(smc+OFF_SAC))[tid];
  }
}

// ---------------- att2 wmma kernel (softmax + V-agg + residual) -------------
__global__ void __launch_bounds__(256, 1) k_att2_w(const float* __restrict__ W) {
  char* smc = (char*)dsm;
  int tid = threadIdx.x, b = blockIdx.y;
  int warp = tid >> 5, lane = tid & 31;
  if (tid < 128)
    ((float2*)(smc+OFF_CO))[tid] = make_float2(g_sc2[b*CC+tid], g_sh2[b*CC+tid]);
  build_wtile(W, smc, tid);
  int row = tid >> 1, half = tid & 1;
  int sub = warp & 3, cb = (warp >> 2)*64;
  int er = sub*32 + lane, kk = er & 15;
  __nv_bfloat16* Ahp = (__nv_bfloat16*)(smc+OFF_AH) + row*PA + half*64;
  __nv_bfloat16* Alp = (__nv_bfloat16*)(smc+OFF_AL) + row*PA + half*64;
  const float* Drow = (const float*)(smc+OFF_D) + (size_t)er*PD + cb;
  for (int tl = blockIdx.x; tl < 1024; tl += gridDim.x) {
    int n0 = tl*8;
    size_t r0 = ((size_t)b*NN + n0)*16;
    __syncthreads();
    if (tid < 128) ((int*)(smc+OFF_JSH))[tid] = g_idx[r0 + tid];
    {
      const float4* tp = (const float4*)(g_t1 + (r0 + row)*CC + half*64);
      const float2* c2 = (const float2*)(smc+OFF_CO) + half*64;
      #pragma unroll
      for (int cc = 0; cc < 8; cc++) {
        float4 f0 = tp[cc*2], f1 = tp[cc*2+1];
        float v[8] = {f0.x,f0.y,f0.z,f0.w,f1.x,f1.y,f1.z,f1.w};
        #pragma unroll
        for (int i = 0; i < 8; i++) {
          float2 c = c2[cc*8+i];
          float y = fmaf(c.x, v[i], c.y);
          v[i] = (y >= 0.f) ? y : 0.1f*y;
        }
        uint4 hi, lo; SPLIT8(v, hi, lo);
        *(uint4*)(Ahp + cc*8) = hi;
        *(uint4*)(Alp + cc*8) = lo;
      }
    }
    __syncthreads();
    wmma_gemm(smc, warp);
    __syncthreads();
    float a[64];
    #pragma unroll
    for (int q = 0; q < 64; q++) {
      float x = Drow[q];
      float m = x;
      #pragma unroll
      for (int off = 8; off >= 1; off >>= 1) m = fmaxf(m, __shfl_xor_sync(0xffffffffu, m, off, 16));
      float e = __expf(x - m);
      float s = e;
      #pragma unroll
      for (int off = 8; off >= 1; off >>= 1) s += __shfl_xor_sync(0xffffffffu, s, off, 16);
      a[q] = e / s;
    }
    int nq = n0 + (er >> 4), j = ((int*)(smc+OFF_JSH))[er];
    const float4* vp = (const float4*)(g_v + ((size_t)b*NN + j)*CC + cb);
    const float4* np = (const float4*)(g_nf + ((size_t)b*NN + nq)*CC + cb);
    float4* yp = (float4*)(g_y5 + ((size_t)b*NN + nq)*CC + cb);
    #pragma unroll
    for (int q4 = 0; q4 < 16; q4++) {
      float4 vv = vp[q4], oo;
      oo.x = a[q4*4+0]*vv.x; oo.y = a[q4*4+1]*vv.y;
      oo.z = a[q4*4+2]*vv.z; oo.w = a[q4*4+3]*vv.w;
      #pragma unroll
      for (int off = 8; off >= 1; off >>= 1) {
        oo.x += __shfl_xor_sync(0xffffffffu, oo.x, off, 16);
        oo.y += __shfl_xor_sync(0xffffffffu, oo.y, off, 16);
        oo.z += __shfl_xor_sync(0xffffffffu, oo.z, off, 16);
        oo.w += __shfl_xor_sync(0xffffffffu, oo.w, off, 16);
      }
      if (kk == 0) {
        float4 nf = np[q4], r;
        r.x = oo.x + nf.x; r.y = oo.y + nf.y; r.z = oo.z + nf.z; r.w = oo.w + nf.w;
        yp[q4] = r;
      }
    }
  }
}

// ---------------- post conv + stats -----------------------------------------
__global__ void __launch_bounds__(256) k_conv_post(const float* __restrict__ X,
                                                   const float* __restrict__ W,
                                                   const float* __restrict__ bias,
                                                   float* __restrict__ Y) {
  float* wr = dsm;
  float* gb = dsm + CC*129;
  float* sacc = gb + 2*CC*20;
  int tid = threadIdx.x, grp = tid >> 7, co = tid & 127, lane = tid & 31;
  int b = blockIdx.y;
  for (int e = tid; e < CC*CC; e += 256) wr[(e>>7)*129 + (e&127)] = W[e];
  if (tid < 16) sacc[tid] = 0.f;
  float bv = bias[co];
  float* g = gb + grp*(CC*20);
  float ts = 0.f, tss = 0.f;
  for (int it = 0; it < 2; it++) {
    size_t r0 = (size_t)b*NN + (size_t)(blockIdx.x*2 + it)*32 + grp*16;
    __syncthreads();
    #pragma unroll
    for (int p = 0; p < 16; p++) g[co*20+p] = X[(r0+p)*CC + co];
    __syncthreads();
    float acc[16];
    #pragma unroll
    for (int p = 0; p < 16; p++) acc[p] = bv;
    #pragma unroll 4
    for (int ci = 0; ci < CC; ci++) { float w = wr[co*129+ci]; GSTEP16(w, g + ci*20); }
    #pragma unroll
    for (int p = 0; p < 16; p++) { Y[(r0+p)*CC + co] = acc[p]; ts += acc[p]; tss = fmaf(acc[p],acc[p],tss); }
  }
  #pragma unroll
  for (int off = 8; off >= 1; off >>= 1) {
    ts  += __shfl_down_sync(0xffffffffu, ts, off, 16);
    tss += __shfl_down_sync(0xffffffffu, tss, off, 16);
  }
  if ((lane & 15) == 0) {
    int cgg = co >> 4;
    atomicAdd(&sacc[cgg], ts); atomicAdd(&sacc[8+cgg], tss);
  }
  __syncthreads();
  if (tid < 16) g_part3[((size_t)b*gridDim.x + blockIdx.x)*16 + tid] = sacc[tid];
}

// ---------------- final GN3 + lrelu + transpose -----------------------------
__global__ void k_final(float* __restrict__ out) {
  __shared__ float t[32][33];
  int b = blockIdx.z, c0 = blockIdx.y*32, n0 = blockIdx.x*32;
  int tx = threadIdx.x, ty = threadIdx.y;
  float scv = g_sc3[b*CC + c0 + tx], shv = g_sh3[b*CC + c0 + tx];
  #pragma unroll
  for (int i = 0; i < 4; i++) {
    int n = n0 + ty*4 + i;
    float x = g_aq[((size_t)b*NN + n)*CC + c0 + tx];
    float y = fmaf(scv, x, shv);
    t[tx][ty*4+i] = (y >= 0.f) ? y : 0.1f*y;
  }
  __syncthreads();
  #pragma unroll
  for (int i = 0; i < 4; i++) {
    int c = c0 + ty*4 + i;
    out[((size_t)b*CC + c)*NN + n0 + tx] = t[ty*4+i][tx];
  }
}

// ---------------- launch ----------------------------------------------------
extern "C" void kernel_launch(void* const* d_in, const int* in_sizes, int n_in,
                              void* d_out, int out_size) {
  const float* xyz    = (const float*)d_in[0];
  const float* feat   = (const float*)d_in[1];
  const float* pre_w  = (const float*)d_in[2];
  const float* pre_b  = (const float*)d_in[3];
  const float* wq_w   = (const float*)d_in[4];
  const float* wq_b   = (const float*)d_in[5];
  const float* wk_w   = (const float*)d_in[6];
  const float* wk_b   = (const float*)d_in[7];
  const float* wv_w   = (const float*)d_in[8];
  const float* wv_b   = (const float*)d_in[9];
  const float* pos1_w = (const float*)d_in[10];
  const float* pos1_b = (const float*)d_in[11];
  const float* pos1_g = (const float*)d_in[12];
  const float* pos1_be= (const float*)d_in[13];
  const float* att1_b = (const float*)d_in[17];
  const float* att1_g = (const float*)d_in[18];
  const float* att1_be= (const float*)d_in[19];
  const float* att2_w = (const float*)d_in[20];
  const float* post_w = (const float*)d_in[22];
  const float* post_b = (const float*)d_in[23];
  const float* post_g = (const float*)d_in[24];
  const float* post_be= (const float*)d_in[25];
  float* out = (float*)d_out;

  const int SMEMC = (CC*129 + 2*CC*20 + 16) * 4;
  cudaFuncSetAttribute(k_convQKV,  cudaFuncAttributeMaxDynamicSharedMemorySize, SMEMC);
  cudaFuncSetAttribute(k_conv_post,cudaFuncAttributeMaxDynamicSharedMemorySize, SMEMC);
  cudaFuncSetAttribute(k_att1_w,   cudaFuncAttributeMaxDynamicSharedMemorySize, SMT);
  cudaFuncSetAttribute(k_att2_w,   cudaFuncAttributeMaxDynamicSharedMemorySize, SMT);

  // device addresses via the runtime — NEVER pass __device__ symbols directly
  void *p_y5, *p_aq;
  cudaGetSymbolAddress(&p_y5, g_y5);
  cudaGetSymbolAddress(&p_aq, g_aq);

  k_knn<<<dim3(NN/128, BB), 128>>>(xyz);
  k_pre<<<dim3(NN/32, BB), 256>>>(feat, pre_w, pre_b);
  k_combine<<<4, 256>>>((const float*)d_in[16], wq_w, wk_w, (const float*)d_in[14],
                        att1_b, wq_b, wk_b, (const float*)d_in[15]);
  k_convQKV<<<dim3(128, BB, 3), 256, SMEMC>>>(wv_w, att1_b, wv_b);   // 4th = profiled slot
  k_gn1<<<1024, 256>>>(xyz, pos1_w, pos1_b);
  k_reduce<<<2, 256>>>(0, 512, 1.f/2097152.f, pos1_g, pos1_be);
  k_att1_w<<<dim3(74, BB), 256, SMT>>>(xyz, pos1_w, pos1_b);
  k_reduce<<<2, 256>>>(1, 1024, 1.f/2097152.f, att1_g, att1_be);
  k_att2_w<<<dim3(74, BB), 256, SMT>>>(att2_w);
  k_conv_post<<<dim3(128, BB), 256, SMEMC>>>((const float*)p_y5, post_w, post_b, (float*)p_aq);
  k_reduce<<<2, 256>>>(2, 128, 1.f/131072.f, post_g, post_be);
  k_final<<<dim3(NN/32, CC/32, BB), dim3(32, 8)>>>(out);
}